// round 8
// baseline (speedup 1.0000x reference)
#include <cuda_runtime.h>
#include <cuda_bf16.h>
#include <math.h>
#include <stdint.h>

#define B_    8
#define L_    2048
#define DM    1000
#define ED    2000
#define NSTATE 8
#define DTR   63
#define NXP   79
#define NOUT  64
#define ROWS  (B_*L_)
#define GK    1024
#define GN    4096
#define CH    8
#define TCH   (L_/CH)

// GEMM smem: 2 stages x 4 tiles x (128 rows x 80B)
#define RSTRIDE 80
#define TILE_B  (128*RSTRIDE)
#define STAGE_B (4*TILE_B)
#define GEMM_SMEM (2*STAGE_B)

__device__ __align__(128) __nv_bfloat16 g_Ah[(size_t)ROWS*GK];
__device__ __align__(128) __nv_bfloat16 g_Al[(size_t)ROWS*GK];
__device__ __align__(128) __nv_bfloat16 g_Wh[(size_t)GN*GK];
__device__ __align__(128) __nv_bfloat16 g_Wl[(size_t)GN*GK];
__device__ __align__(128) float g_xcin [(size_t)ROWS*ED];
__device__ __align__(128) float g_sz   [(size_t)ROWS*ED];
__device__ __align__(128) float g_xcs  [(size_t)ROWS*ED];
__device__ __align__(128) float g_delta[(size_t)ROWS*ED];
__device__ __align__(128) float g_dbc  [(size_t)ROWS*NXP];
__device__ __align__(128) float g_sacc [B_*CH*ED];
__device__ __align__(128) float g_sP   [B_*CH*NSTATE*ED];
__device__ __align__(128) float g_sr   [B_*CH*NSTATE*ED];
__device__ __align__(128) float g_sq   [B_*CH*NSTATE*ED];
__device__ __align__(128) float g_ybar [B_*ED];
__device__ __align__(128) float g_xbar [B_*DM];
__device__ __align__(128) float g_e    [B_*DM];

// ---------------- fast math (FMA pipe, no MUFU) -----------------------------
__device__ __forceinline__ float fast_exp(float x) {
    float t = x * 1.4426950408889634f;
    t = fminf(fmaxf(t, -125.f), 125.f);
    float r = rintf(t);
    float f = t - r;
    float p =             1.3333558e-3f;
    p = fmaf(p, f, 9.6181291e-3f);
    p = fmaf(p, f, 5.5504109e-2f);
    p = fmaf(p, f, 2.4022651e-1f);
    p = fmaf(p, f, 6.9314718e-1f);
    p = fmaf(p, f, 1.0f);
    return p * __int_as_float(((int)r + 127) << 23);
}
__device__ __forceinline__ float fast_rcp12(float d) { // 1/d, d in (1,2]
    float r = fmaf(d, -0.47058824f, 1.4117647f);
    r = r * fmaf(-d, r, 2.0f);
    r = r * fmaf(-d, r, 2.0f);
    return r;
}
__device__ __forceinline__ float fast_silu(float v) {
    float t = fast_exp(-fabsf(v));
    float r = fast_rcp12(1.0f + t);
    return (v >= 0.f) ? v * r : v * t * r;
}
__device__ __forceinline__ float fast_softplus(float u) {
    if (u > 15.f) return u;
    float v = 1.0f + fast_exp(u);
    int bi = __float_as_int(v);
    int e = ((bi >> 23) & 255) - 127;
    float m = __int_as_float((bi & 0x007FFFFF) | 0x3F800000);
    if (m > 1.4142135f) { m *= 0.5f; e += 1; }
    float x = m - 1.0f;
    float q = -0.1f;
    q = fmaf(q, x,  0.111111111f);
    q = fmaf(q, x, -0.125f);
    q = fmaf(q, x,  0.142857143f);
    q = fmaf(q, x, -0.166666667f);
    q = fmaf(q, x,  0.2f);
    q = fmaf(q, x, -0.25f);
    q = fmaf(q, x,  0.333333333f);
    q = fmaf(q, x, -0.5f);
    q = fmaf(q, x,  1.0f);
    return fmaf((float)e, 0.69314718056f, q * x);
}

// ---------------- PTX helpers (compute_103-safe: no tcgen05) ----------------
__device__ __forceinline__ uint32_t smem_u32(const void* p) {
    uint32_t a;
    asm("{ .reg .u64 t; cvta.to.shared.u64 t, %1; cvt.u32.u64 %0, t; }" : "=r"(a) : "l"(p));
    return a;
}
#define CP_ASYNC16(sa, ga) asm volatile("cp.async.cg.shared.global [%0], [%1], 16;" :: "r"(sa), "l"(ga))
#define CP_COMMIT()        asm volatile("cp.async.commit_group;")
#define CP_WAIT0()         asm volatile("cp.async.wait_group 0;")
#define CP_WAIT1()         asm volatile("cp.async.wait_group 1;")
#define LDSM_X4(r, addr) \
    asm volatile("ldmatrix.sync.aligned.m8n8.x4.shared.b16 {%0,%1,%2,%3}, [%4];" \
        : "=r"((r)[0]), "=r"((r)[1]), "=r"((r)[2]), "=r"((r)[3]) : "r"(addr))
#define MMA16816(d, a, b0, b1) \
    asm volatile("mma.sync.aligned.m16n8k16.row.col.f32.bf16.bf16.f32 " \
        "{%0,%1,%2,%3}, {%4,%5,%6,%7}, {%8,%9}, {%0,%1,%2,%3};" \
        : "+f"((d)[0]), "+f"((d)[1]), "+f"((d)[2]), "+f"((d)[3]) \
        : "r"((a)[0]), "r"((a)[1]), "r"((a)[2]), "r"((a)[3]), "r"(b0), "r"(b1))

// ---------------- rmsnorm + bf16 hi/lo convert ------------------------------
__global__ void rms_cvt_kernel(const float* __restrict__ x, const float* __restrict__ w) {
    int row = blockIdx.x;
    int tid = threadIdx.x;
    const float* xr = x + (size_t)row * DM;
    float s = 0.f;
    for (int d = tid; d < DM; d += 256) { float v = xr[d]; s += v * v; }
    __shared__ float red[256];
    red[tid] = s; __syncthreads();
    for (int st = 128; st > 0; st >>= 1) {
        if (tid < st) red[tid] += red[tid + st];
        __syncthreads();
    }
    float rstd = rsqrtf(red[0] * (1.f / DM) + 1e-5f);
    __nv_bfloat16* oh = g_Ah + (size_t)row * GK;
    __nv_bfloat16* ol = g_Al + (size_t)row * GK;
    for (int d = tid; d < GK; d += 256) {
        float v = (d < DM) ? xr[d] * rstd * w[d] : 0.f;
        __nv_bfloat16 h = __float2bfloat16(v);
        oh[d] = h;
        ol[d] = __float2bfloat16(v - __bfloat162float(h));
    }
}

// ---------------- W_in transpose + hi/lo convert ----------------------------
__global__ void wcvt_kernel(const float* __restrict__ W_in) {
    int idx = blockIdx.x * 256 + threadIdx.x;
    if (idx >= GN * GK) return;
    int n = idx >> 10;
    int k = idx & (GK - 1);
    float v = (n < 2 * ED && k < DM) ? W_in[(size_t)k * (2 * ED) + n] : 0.f;
    __nv_bfloat16 h = __float2bfloat16(v);
    g_Wh[idx] = h;
    g_Wl[idx] = __float2bfloat16(v - __bfloat162float(h));
}

// ---------------- mma.sync bf16 GEMM: xz = xn @ W_in ------------------------
// C[16384 x 4096] = A[16384 x 1024] * W^T (W stored [n][k]).
// 3-term hi/lo split for ~fp32 accuracy. Split epilogue: xc | silu(z).
__global__ void __launch_bounds__(256)
gemm_mma_kernel(const __nv_bfloat16* __restrict__ Ah, const __nv_bfloat16* __restrict__ Al,
                const __nv_bfloat16* __restrict__ Bh, const __nv_bfloat16* __restrict__ Bl,
                float* __restrict__ xcout, float* __restrict__ szout)
{
    extern __shared__ char smem[];
    const uint32_t sbase = smem_u32(smem);
    const int tid = threadIdx.x;
    const int wid = tid >> 5, lane = tid & 31;
    const int m0 = blockIdx.y * 128;
    const int n0 = blockIdx.x * 128;
    const int wm = (wid >> 2) * 64;
    const int wn = (wid & 3) * 32;

    float acc[4][4][4];
    #pragma unroll
    for (int i = 0; i < 4; i++)
        #pragma unroll
        for (int j = 0; j < 4; j++)
            #pragma unroll
            for (int v = 0; v < 4; v++) acc[i][j][v] = 0.f;

    // per-thread load slots: id in [0,512): row=id>>2, chunk=id&3
    const int r0l = tid >> 2, c0l = (tid & 3);
    const int r1l = (tid + 256) >> 2, c1l = ((tid + 256) & 3);

    const int NIT = GK / 32;
    #pragma unroll 1
    for (int it = 0; it < NIT + 1; it++) {
        if (it < NIT) {  // issue async loads for stage `it`
            const int k0 = it * 32;
            const uint32_t sb = sbase + (it & 1) * STAGE_B;
            {
                uint32_t so = (uint32_t)(r0l * RSTRIDE + c0l * 16);
                size_t ga = (size_t)(m0 + r0l) * GK + k0 + c0l * 8;
                size_t gb = (size_t)(n0 + r0l) * GK + k0 + c0l * 8;
                CP_ASYNC16(sb + 0 * TILE_B + so, Ah + ga);
                CP_ASYNC16(sb + 1 * TILE_B + so, Al + ga);
                CP_ASYNC16(sb + 2 * TILE_B + so, Bh + gb);
                CP_ASYNC16(sb + 3 * TILE_B + so, Bl + gb);
            }
            {
                uint32_t so = (uint32_t)(r1l * RSTRIDE + c1l * 16);
                size_t ga = (size_t)(m0 + r1l) * GK + k0 + c1l * 8;
                size_t gb = (size_t)(n0 + r1l) * GK + k0 + c1l * 8;
                CP_ASYNC16(sb + 0 * TILE_B + so, Ah + ga);
                CP_ASYNC16(sb + 1 * TILE_B + so, Al + ga);
                CP_ASYNC16(sb + 2 * TILE_B + so, Bh + gb);
                CP_ASYNC16(sb + 3 * TILE_B + so, Bl + gb);
            }
            CP_COMMIT();
        }
        if (it == 0) continue;
        // compute stage it-1
        if (it < NIT) CP_WAIT1(); else CP_WAIT0();
        __syncthreads();
        const uint32_t sb = sbase + ((it - 1) & 1) * STAGE_B;
        const uint32_t sA_h = sb, sA_l = sb + TILE_B, sB_h = sb + 2 * TILE_B, sB_l = sb + 3 * TILE_B;

        // ldmatrix address offsets
        const uint32_t a_row = (uint32_t)(wm + (lane & 15));
        const uint32_t a_kb  = (uint32_t)(((lane >> 4) << 3) * 2);
        const uint32_t b_row = (uint32_t)(wn + ((lane >> 4) << 3) + (lane & 7));
        const uint32_t b_kb  = (uint32_t)((((lane >> 3) & 1) * 8) * 2);

        #pragma unroll
        for (int ks = 0; ks < 2; ks++) {
            const uint32_t kb = (uint32_t)(ks * 32);
            uint32_t ah[4][4], al[4][4], bh[2][4], bl[2][4];
            #pragma unroll
            for (int mt = 0; mt < 4; mt++) {
                uint32_t ad = (a_row + mt * 16) * RSTRIDE + kb + a_kb;
                LDSM_X4(ah[mt], sA_h + ad);
                LDSM_X4(al[mt], sA_l + ad);
            }
            #pragma unroll
            for (int p = 0; p < 2; p++) {
                uint32_t bd = (b_row + p * 16) * RSTRIDE + kb + b_kb;
                LDSM_X4(bh[p], sB_h + bd);
                LDSM_X4(bl[p], sB_l + bd);
            }
            #pragma unroll
            for (int mt = 0; mt < 4; mt++)
                #pragma unroll
                for (int nt = 0; nt < 4; nt++) {
                    const int p = nt >> 1, o = (nt & 1) * 2;
                    MMA16816(acc[mt][nt], ah[mt], bh[p][o], bh[p][o + 1]);
                    MMA16816(acc[mt][nt], ah[mt], bl[p][o], bl[p][o + 1]);
                    MMA16816(acc[mt][nt], al[mt], bh[p][o], bh[p][o + 1]);
                }
        }
        __syncthreads();
    }

    // epilogue: d0,d1 -> (row, col..col+1), d2,d3 -> (row+8, col..col+1)
    #pragma unroll
    for (int mt = 0; mt < 4; mt++) {
        int row = m0 + wm + mt * 16 + (lane >> 2);
        #pragma unroll
        for (int nt = 0; nt < 4; nt++) {
            int col = n0 + wn + nt * 8 + (lane & 3) * 2;
            #pragma unroll
            for (int half = 0; half < 2; half++) {
                int rr = row + half * 8;
                float v0 = acc[mt][nt][half * 2 + 0];
                float v1 = acc[mt][nt][half * 2 + 1];
                if (col < 2000) {
                    float2 f = make_float2(v0, v1);
                    *reinterpret_cast<float2*>(xcout + (size_t)rr * ED + col) = f;
                } else if (col < 4000) {
                    float2 f = make_float2(fast_silu(v0), fast_silu(v1));
                    *reinterpret_cast<float2*>(szout + (size_t)rr * ED + (col - 2000)) = f;
                }
            }
        }
    }
}

// ---------------- fp32 SGEMM (xproj, delta) ---------------------------------
__global__ void __launch_bounds__(256, 2)
sgemm(const float* __restrict__ A, const float* __restrict__ B,
      int M, int N, int K, int lda, int ldb, int ldc,
      float* __restrict__ C1, const float* __restrict__ bias, int mode)
{
    constexpr int BM = 128, BN = 128, BK = 16, TM = 8, TN = 8;
    __shared__ float As[BK][BM + 4];
    __shared__ float Bs[BK][BN];
    const int t = threadIdx.x;
    const int row0 = blockIdx.y * BM;
    const int col0 = blockIdx.x * BN;
    const int aRow = t >> 2, aCol = (t & 3) * 4;
    const int bRow = t >> 5, bCol = (t & 31) * 4;
    const int ty = t >> 4, tx = t & 15;

    float acc[TM][TN];
    #pragma unroll
    for (int i = 0; i < TM; i++)
        #pragma unroll
        for (int j = 0; j < TN; j++) acc[i][j] = 0.f;

    for (int k0 = 0; k0 < K; k0 += BK) {
        #pragma unroll
        for (int s = 0; s < 2; s++) {
            int r = aRow + s * 64;
            int gk = k0 + aCol;
            float4 v = make_float4(0.f, 0.f, 0.f, 0.f);
            const float* ap = A + (size_t)(row0 + r) * lda + gk;
            if (gk + 0 < K) v.x = ap[0];
            if (gk + 1 < K) v.y = ap[1];
            if (gk + 2 < K) v.z = ap[2];
            if (gk + 3 < K) v.w = ap[3];
            As[aCol + 0][r] = v.x;
            As[aCol + 1][r] = v.y;
            As[aCol + 2][r] = v.z;
            As[aCol + 3][r] = v.w;
        }
        #pragma unroll
        for (int s = 0; s < 2; s++) {
            int r = bRow + s * 8;
            int gk = k0 + r;
            int gc = col0 + bCol;
            float4 v = make_float4(0.f, 0.f, 0.f, 0.f);
            const float* bp = B + (size_t)gk * ldb + gc;
            if (gk < K) {
                if (gc + 0 < N) v.x = bp[0];
                if (gc + 1 < N) v.y = bp[1];
                if (gc + 2 < N) v.z = bp[2];
                if (gc + 3 < N) v.w = bp[3];
            }
            *reinterpret_cast<float4*>(&Bs[r][bCol]) = v;
        }
        __syncthreads();
        #pragma unroll
        for (int kk = 0; kk < BK; kk++) {
            float ra[TM], rb[TN];
            const float4* a4 = reinterpret_cast<const float4*>(&As[kk][ty * TM]);
            float4 a0 = a4[0], a1 = a4[1];
            ra[0]=a0.x; ra[1]=a0.y; ra[2]=a0.z; ra[3]=a0.w;
            ra[4]=a1.x; ra[5]=a1.y; ra[6]=a1.z; ra[7]=a1.w;
            const float4* b4 = reinterpret_cast<const float4*>(&Bs[kk][tx * TN]);
            float4 b0 = b4[0], b1 = b4[1];
            rb[0]=b0.x; rb[1]=b0.y; rb[2]=b0.z; rb[3]=b0.w;
            rb[4]=b1.x; rb[5]=b1.y; rb[6]=b1.z; rb[7]=b1.w;
            #pragma unroll
            for (int i = 0; i < TM; i++)
                #pragma unroll
                for (int j = 0; j < TN; j++)
                    acc[i][j] = fmaf(ra[i], rb[j], acc[i][j]);
        }
        __syncthreads();
    }
    #pragma unroll
    for (int i = 0; i < TM; i++) {
        int gr = row0 + ty * TM + i;
        #pragma unroll
        for (int j = 0; j < TN; j++) {
            int gc = col0 + tx * TN + j;
            if (gc >= N) continue;
            float v = acc[i][j];
            if (mode == 0) C1[(size_t)gr * ldc + gc] = v;
            else           C1[(size_t)gr * ldc + gc] = fast_softplus(v + bias[gc]);
        }
    }
}

// ---------------- depthwise causal conv1d + silu ----------------------------
__global__ void conv_silu_kernel(const float* __restrict__ cw, const float* __restrict__ cb) {
    size_t idx = (size_t)blockIdx.x * blockDim.x + threadIdx.x;
    if (idx >= (size_t)ROWS * ED) return;
    int e = (int)(idx % ED);
    size_t bl = idx / ED;
    int l = (int)(bl % L_);
    float acc = cb[e];
    #pragma unroll
    for (int k = 0; k < 4; k++) {
        int ls = l - 3 + k;
        if (ls >= 0)
            acc = fmaf(g_xcin[idx + (size_t)(ls - l) * ED], cw[e * 4 + k], acc);
    }
    g_xcs[idx] = fast_silu(acc);
}

// ---------------- chunked selective scan: part 1 ----------------------------
__global__ void scan1_kernel(const float* __restrict__ A_log, const float* __restrict__ Dp) {
    int e = blockIdx.x * 256 + threadIdx.x;
    int b = blockIdx.y;
    int c = blockIdx.z;
    if (e >= ED) return;
    float A[NSTATE], h[NSTATE], cum[NSTATE], rr[NSTATE];
    #pragma unroll
    for (int n = 0; n < NSTATE; n++) {
        A[n] = -__expf(A_log[e * NSTATE + n]);
        h[n] = 0.f; cum[n] = 1.f; rr[n] = 0.f;
    }
    float dpe = Dp[e];
    float lacc = 0.f;
    size_t base = ((size_t)(b * L_ + c * TCH)) * ED + e;
    const float* dbcr = g_dbc + (size_t)(b * L_ + c * TCH) * NXP;
    for (int l = 0; l < TCH; l++) {
        float d   = g_delta[base];
        float xv  = g_xcs[base];
        float szv = g_sz[base];
        float dx = d * xv;
        float y = 0.f;
        #pragma unroll
        for (int n = 0; n < NSTATE; n++) {
            float Bn = dbcr[DTR + n];
            float Cn = dbcr[DTR + NSTATE + n];
            float a = fast_exp(d * A[n]);
            cum[n] *= a;
            h[n] = fmaf(a, h[n], dx * Bn);
            y = fmaf(h[n], Cn, y);
            rr[n] = fmaf(cum[n], Cn * szv, rr[n]);
        }
        lacc = fmaf(y + dpe * xv, szv, lacc);
        base += ED;
        dbcr += NXP;
    }
    int bc = b * CH + c;
    g_sacc[bc * ED + e] = lacc;
    #pragma unroll
    for (int n = 0; n < NSTATE; n++) {
        size_t o = ((size_t)bc * NSTATE + n) * ED + e;
        g_sP[o] = cum[n];
        g_sr[o] = rr[n];
        g_sq[o] = h[n];
    }
}

// ---------------- chunked selective scan: part 2 ----------------------------
__global__ void scan2_kernel() {
    int idx = blockIdx.x * 256 + threadIdx.x;
    if (idx >= B_ * ED) return;
    int b = idx / ED, e = idx % ED;
    float h[NSTATE];
    #pragma unroll
    for (int n = 0; n < NSTATE; n++) h[n] = 0.f;
    float acc = 0.f;
    for (int c = 0; c < CH; c++) {
        int bc = b * CH + c;
        acc += g_sacc[bc * ED + e];
        #pragma unroll
        for (int n = 0; n < NSTATE; n++) {
            size_t o = ((size_t)bc * NSTATE + n) * ED + e;
            acc = fmaf(h[n], g_sr[o], acc);
            h[n] = fmaf(g_sP[o], h[n], g_sq[o]);
        }
    }
    g_ybar[idx] = acc * (1.0f / L_);
}

// ---------------- tail kernels ----------------------------------------------
__global__ void xbar_kernel(const float* __restrict__ x) {
    int idx = blockIdx.x * blockDim.x + threadIdx.x;
    if (idx >= B_ * DM) return;
    int b = idx / DM, d = idx % DM;
    const float* p = x + (size_t)b * L_ * DM + d;
    float s = 0.f;
    #pragma unroll 8
    for (int l = 0; l < L_; l++) s += p[(size_t)l * DM];
    g_xbar[idx] = s * (1.f / L_);
}

__global__ void out_e_kernel(const float* __restrict__ W_outp) {
    int idx = blockIdx.x * blockDim.x + threadIdx.x;
    if (idx >= B_ * DM) return;
    int b = idx / DM, d = idx % DM;
    float acc = g_xbar[idx];
    const float* yb = g_ybar + b * ED;
    #pragma unroll 8
    for (int e = 0; e < ED; e++)
        acc = fmaf(yb[e], W_outp[(size_t)e * DM + d], acc);
    g_e[idx] = acc;
}

__global__ void out_h_kernel(const float* __restrict__ W_fc, const float* __restrict__ b_fc,
                             float* __restrict__ out) {
    int idx = blockIdx.x * blockDim.x + threadIdx.x;
    if (idx >= B_ * DM) return;
    int b = idx / DM, d = idx % DM;
    float acc = b_fc[d];
    const float* er = g_e + b * DM;
    #pragma unroll 8
    for (int k = 0; k < DM; k++)
        acc = fmaf(er[k], W_fc[(size_t)k * DM + d], acc);
    float th = tanhf(acc);
    out[idx] = (th > 0.f) ? th : expm1f(th);
}

__global__ void out_musig_kernel(const float* __restrict__ W_mu, const float* __restrict__ b_mu,
                                 const float* __restrict__ W_sig, const float* __restrict__ b_sig,
                                 float* __restrict__ out) {
    int idx = blockIdx.x * blockDim.x + threadIdx.x;
    if (idx >= B_ * 2 * NOUT) return;
    int b = idx / (2 * NOUT);
    int r = idx % (2 * NOUT);
    const float* h = out + b * DM;
    if (r < NOUT) {
        float acc = b_mu[r];
        #pragma unroll 8
        for (int k = 0; k < DM; k++)
            acc = fmaf(h[k], W_mu[(size_t)k * NOUT + r], acc);
        out[B_ * DM + b * NOUT + r] = acc;
    } else {
        int j = r - NOUT;
        float acc = b_sig[j];
        #pragma unroll 8
        for (int k = 0; k < DM; k++)
            acc = fmaf(h[k], W_sig[(size_t)k * NOUT + j], acc);
        float el = (acc > 0.f) ? acc : expm1f(acc);
        out[B_ * DM + B_ * NOUT + b * NOUT + j] = el + 1.0f + 1e-14f;
    }
}

// ---------------- launcher ----------------------------------------------------
extern "C" void kernel_launch(void* const* d_in, const int* in_sizes, int n_in,
                              void* d_out, int out_size) {
    (void)in_sizes; (void)n_in; (void)out_size;
    const float* x      = (const float*)d_in[0];
    const float* w_norm = (const float*)d_in[1];
    const float* W_in   = (const float*)d_in[2];
    const float* conv_w = (const float*)d_in[3];
    const float* conv_b = (const float*)d_in[4];
    const float* W_xproj= (const float*)d_in[5];
    const float* W_dt   = (const float*)d_in[6];
    const float* b_dt   = (const float*)d_in[7];
    const float* A_log  = (const float*)d_in[8];
    const float* Dp     = (const float*)d_in[9];
    const float* W_outp = (const float*)d_in[10];
    const float* W_fc   = (const float*)d_in[11];
    const float* b_fc   = (const float*)d_in[12];
    const float* W_mu   = (const float*)d_in[13];
    const float* b_mu   = (const float*)d_in[14];
    const float* W_sig  = (const float*)d_in[15];
    const float* b_sig  = (const float*)d_in[16];
    float* out = (float*)d_out;

    float *p_xcin, *p_sz, *p_xcs, *p_delta, *p_dbc;
    __nv_bfloat16 *p_Ah, *p_Al, *p_Wh, *p_Wl;
    cudaGetSymbolAddress((void**)&p_xcin,  g_xcin);
    cudaGetSymbolAddress((void**)&p_sz,    g_sz);
    cudaGetSymbolAddress((void**)&p_xcs,   g_xcs);
    cudaGetSymbolAddress((void**)&p_delta, g_delta);
    cudaGetSymbolAddress((void**)&p_dbc,   g_dbc);
    cudaGetSymbolAddress((void**)&p_Ah,    g_Ah);
    cudaGetSymbolAddress((void**)&p_Al,    g_Al);
    cudaGetSymbolAddress((void**)&p_Wh,    g_Wh);
    cudaGetSymbolAddress((void**)&p_Wl,    g_Wl);

    cudaFuncSetAttribute(gemm_mma_kernel, cudaFuncAttributeMaxDynamicSharedMemorySize, GEMM_SMEM);

    // 1) rmsnorm + bf16 hi/lo A
    rms_cvt_kernel<<<ROWS, 256>>>(x, w_norm);
    // 2) W_in transpose + bf16 hi/lo
    wcvt_kernel<<<(GN * GK + 255) / 256, 256>>>(W_in);
    // 3) xz = xn @ W_in via mma.sync (split xc | silu(z))
    {
        dim3 grid(GN / 128, ROWS / 128);
        gemm_mma_kernel<<<grid, 256, GEMM_SMEM>>>(p_Ah, p_Al, p_Wh, p_Wl, p_xcin, p_sz);
    }
    // 4) depthwise causal conv + silu
    {
        size_t total = (size_t)ROWS * ED;
        conv_silu_kernel<<<(unsigned)((total + 255) / 256), 256>>>(conv_w, conv_b);
    }
    // 5) dbc = xcs @ W_xproj
    {
        dim3 grid(1, ROWS / 128);
        sgemm<<<grid, 256>>>(p_xcs, W_xproj, ROWS, NXP, ED, ED, NXP, NXP, p_dbc, nullptr, 0);
    }
    // 6) delta = softplus(dt @ W_dt + b_dt)
    {
        dim3 grid((ED + 127) / 128, ROWS / 128);
        sgemm<<<grid, 256>>>(p_dbc, W_dt, ROWS, ED, DTR, NXP, ED, ED, p_delta, b_dt, 1);
    }
    // 7) chunked scan
    {
        dim3 g1((ED + 255) / 256, B_, CH);
        scan1_kernel<<<g1, 256>>>(A_log, Dp);
        scan2_kernel<<<(B_ * ED + 255) / 256, 256>>>();
    }
    // 8) tails
    xbar_kernel<<<(B_ * DM + 255) / 256, 256>>>(x);
    out_e_kernel<<<(B_ * DM + 255) / 256, 256>>>(W_outp);
    out_h_kernel<<<(B_ * DM + 255) / 256, 256>>>(W_fc, b_fc, out);
    out_musig_kernel<<<(B_ * 2 * NOUT + 255) / 256, 256>>>(W_mu, b_mu, W_sig, b_sig, out);
}

// round 9
// speedup vs baseline: 1.0032x; 1.0032x over previous
#include <cuda_runtime.h>
#include <cuda_bf16.h>
#include <math.h>
#include <stdint.h>

#define B_    8
#define L_    2048
#define DM    1000
#define ED    2000
#define NSTATE 8
#define DTR   63
#define NXP   79
#define NOUT  64
#define ROWS  (B_*L_)
#define GK    1024
#define GN    4096
#define CH    8
#define TCH   (L_/CH)

// GEMM smem: 2 stages x 4 tiles x (128 rows x 80B)
#define RSTRIDE 80
#define TILE_B  (128*RSTRIDE)
#define STAGE_B (4*TILE_B)
#define GEMM_SMEM (2*STAGE_B)

__device__ __align__(128) __nv_bfloat16 g_Ah[(size_t)ROWS*GK];
__device__ __align__(128) __nv_bfloat16 g_Al[(size_t)ROWS*GK];
__device__ __align__(128) __nv_bfloat16 g_Wh[(size_t)GN*GK];
__device__ __align__(128) __nv_bfloat16 g_Wl[(size_t)GN*GK];
__device__ __align__(128) float g_xcin [(size_t)ROWS*ED];
__device__ __align__(128) float g_sz   [(size_t)ROWS*ED];
__device__ __align__(128) float g_xcs  [(size_t)ROWS*ED];
__device__ __align__(128) float g_delta[(size_t)ROWS*ED];
__device__ __align__(128) float g_dbc  [(size_t)ROWS*NXP];
__device__ __align__(128) float g_sacc [B_*CH*ED];
__device__ __align__(128) float g_sP   [B_*CH*NSTATE*ED];
__device__ __align__(128) float g_sr   [B_*CH*NSTATE*ED];
__device__ __align__(128) float g_sq   [B_*CH*NSTATE*ED];
__device__ __align__(128) float g_ybar [B_*ED];
__device__ __align__(128) float g_xbar [B_*DM];
__device__ __align__(128) float g_e    [B_*DM];

// ---------------- fast math (FMA pipe, no MUFU) -----------------------------
__device__ __forceinline__ float fast_exp(float x) {
    float t = x * 1.4426950408889634f;
    t = fminf(fmaxf(t, -125.f), 125.f);
    float r = rintf(t);
    float f = t - r;
    float p =             1.3333558e-3f;
    p = fmaf(p, f, 9.6181291e-3f);
    p = fmaf(p, f, 5.5504109e-2f);
    p = fmaf(p, f, 2.4022651e-1f);
    p = fmaf(p, f, 6.9314718e-1f);
    p = fmaf(p, f, 1.0f);
    return p * __int_as_float(((int)r + 127) << 23);
}
__device__ __forceinline__ float fast_rcp12(float d) { // 1/d, d in (1,2]
    float r = fmaf(d, -0.47058824f, 1.4117647f);
    r = r * fmaf(-d, r, 2.0f);
    r = r * fmaf(-d, r, 2.0f);
    return r;
}
__device__ __forceinline__ float fast_silu(float v) {
    float t = fast_exp(-fabsf(v));
    float r = fast_rcp12(1.0f + t);
    return (v >= 0.f) ? v * r : v * t * r;
}
__device__ __forceinline__ float fast_softplus(float u) {
    if (u > 15.f) return u;
    float v = 1.0f + fast_exp(u);
    int bi = __float_as_int(v);
    int e = ((bi >> 23) & 255) - 127;
    float m = __int_as_float((bi & 0x007FFFFF) | 0x3F800000);
    if (m > 1.4142135f) { m *= 0.5f; e += 1; }
    float x = m - 1.0f;
    float q = -0.1f;
    q = fmaf(q, x,  0.111111111f);
    q = fmaf(q, x, -0.125f);
    q = fmaf(q, x,  0.142857143f);
    q = fmaf(q, x, -0.166666667f);
    q = fmaf(q, x,  0.2f);
    q = fmaf(q, x, -0.25f);
    q = fmaf(q, x,  0.333333333f);
    q = fmaf(q, x, -0.5f);
    q = fmaf(q, x,  1.0f);
    return fmaf((float)e, 0.69314718056f, q * x);
}

// ---------------- PTX helpers (compute_103-safe: no tcgen05) ----------------
__device__ __forceinline__ uint32_t smem_u32(const void* p) {
    uint32_t a;
    asm("{ .reg .u64 t; cvta.to.shared.u64 t, %1; cvt.u32.u64 %0, t; }" : "=r"(a) : "l"(p));
    return a;
}
#define CP_ASYNC16(sa, ga) asm volatile("cp.async.cg.shared.global [%0], [%1], 16;" :: "r"(sa), "l"(ga))
#define CP_COMMIT()        asm volatile("cp.async.commit_group;")
#define CP_WAIT0()         asm volatile("cp.async.wait_group 0;")
#define CP_WAIT1()         asm volatile("cp.async.wait_group 1;")
#define LDSM_X4(r, addr) \
    asm volatile("ldmatrix.sync.aligned.m8n8.x4.shared.b16 {%0,%1,%2,%3}, [%4];" \
        : "=r"((r)[0]), "=r"((r)[1]), "=r"((r)[2]), "=r"((r)[3]) : "r"(addr))
#define MMA16816(d, a, b0, b1) \
    asm volatile("mma.sync.aligned.m16n8k16.row.col.f32.bf16.bf16.f32 " \
        "{%0,%1,%2,%3}, {%4,%5,%6,%7}, {%8,%9}, {%0,%1,%2,%3};" \
        : "+f"((d)[0]), "+f"((d)[1]), "+f"((d)[2]), "+f"((d)[3]) \
        : "r"((a)[0]), "r"((a)[1]), "r"((a)[2]), "r"((a)[3]), "r"(b0), "r"(b1))

// ---------------- rmsnorm + bf16 hi/lo convert ------------------------------
__global__ void rms_cvt_kernel(const float* __restrict__ x, const float* __restrict__ w) {
    int row = blockIdx.x;
    int tid = threadIdx.x;
    const float* xr = x + (size_t)row * DM;
    float s = 0.f;
    for (int d = tid; d < DM; d += 256) { float v = xr[d]; s += v * v; }
    __shared__ float red[256];
    red[tid] = s; __syncthreads();
    for (int st = 128; st > 0; st >>= 1) {
        if (tid < st) red[tid] += red[tid + st];
        __syncthreads();
    }
    float rstd = rsqrtf(red[0] * (1.f / DM) + 1e-5f);
    __nv_bfloat16* oh = g_Ah + (size_t)row * GK;
    __nv_bfloat16* ol = g_Al + (size_t)row * GK;
    for (int d = tid; d < GK; d += 256) {
        float v = (d < DM) ? xr[d] * rstd * w[d] : 0.f;
        __nv_bfloat16 h = __float2bfloat16(v);
        oh[d] = h;
        ol[d] = __float2bfloat16(v - __bfloat162float(h));
    }
}

// ---------------- W_in transpose + hi/lo convert ----------------------------
__global__ void wcvt_kernel(const float* __restrict__ W_in) {
    int idx = blockIdx.x * 256 + threadIdx.x;
    if (idx >= GN * GK) return;
    int n = idx >> 10;
    int k = idx & (GK - 1);
    float v = (n < 2 * ED && k < DM) ? W_in[(size_t)k * (2 * ED) + n] : 0.f;
    __nv_bfloat16 h = __float2bfloat16(v);
    g_Wh[idx] = h;
    g_Wl[idx] = __float2bfloat16(v - __bfloat162float(h));
}

// ---------------- mma.sync bf16 GEMM: xz = xn @ W_in ------------------------
// C[16384 x 4096] = A[16384 x 1024] * W^T (W stored [n][k]).
// 3-term hi/lo split for ~fp32 accuracy. Split epilogue: xc | silu(z).
__global__ void __launch_bounds__(256)
gemm_mma_kernel(const __nv_bfloat16* __restrict__ Ah, const __nv_bfloat16* __restrict__ Al,
                const __nv_bfloat16* __restrict__ Bh, const __nv_bfloat16* __restrict__ Bl,
                float* __restrict__ xcout, float* __restrict__ szout)
{
    extern __shared__ char smem[];
    const uint32_t sbase = smem_u32(smem);
    const int tid = threadIdx.x;
    const int wid = tid >> 5, lane = tid & 31;
    const int m0 = blockIdx.y * 128;
    const int n0 = blockIdx.x * 128;
    const int wm = (wid >> 2) * 64;
    const int wn = (wid & 3) * 32;

    float acc[4][4][4];
    #pragma unroll
    for (int i = 0; i < 4; i++)
        #pragma unroll
        for (int j = 0; j < 4; j++)
            #pragma unroll
            for (int v = 0; v < 4; v++) acc[i][j][v] = 0.f;

    // per-thread load slots: id in [0,512): row=id>>2, chunk=id&3
    const int r0l = tid >> 2, c0l = (tid & 3);
    const int r1l = (tid + 256) >> 2, c1l = ((tid + 256) & 3);

    const int NIT = GK / 32;
    #pragma unroll 1
    for (int it = 0; it < NIT + 1; it++) {
        if (it < NIT) {  // issue async loads for stage `it`
            const int k0 = it * 32;
            const uint32_t sb = sbase + (it & 1) * STAGE_B;
            {
                uint32_t so = (uint32_t)(r0l * RSTRIDE + c0l * 16);
                size_t ga = (size_t)(m0 + r0l) * GK + k0 + c0l * 8;
                size_t gb = (size_t)(n0 + r0l) * GK + k0 + c0l * 8;
                CP_ASYNC16(sb + 0 * TILE_B + so, Ah + ga);
                CP_ASYNC16(sb + 1 * TILE_B + so, Al + ga);
                CP_ASYNC16(sb + 2 * TILE_B + so, Bh + gb);
                CP_ASYNC16(sb + 3 * TILE_B + so, Bl + gb);
            }
            {
                uint32_t so = (uint32_t)(r1l * RSTRIDE + c1l * 16);
                size_t ga = (size_t)(m0 + r1l) * GK + k0 + c1l * 8;
                size_t gb = (size_t)(n0 + r1l) * GK + k0 + c1l * 8;
                CP_ASYNC16(sb + 0 * TILE_B + so, Ah + ga);
                CP_ASYNC16(sb + 1 * TILE_B + so, Al + ga);
                CP_ASYNC16(sb + 2 * TILE_B + so, Bh + gb);
                CP_ASYNC16(sb + 3 * TILE_B + so, Bl + gb);
            }
            CP_COMMIT();
        }
        if (it == 0) continue;
        // compute stage it-1
        if (it < NIT) CP_WAIT1(); else CP_WAIT0();
        __syncthreads();
        const uint32_t sb = sbase + ((it - 1) & 1) * STAGE_B;
        const uint32_t sA_h = sb, sA_l = sb + TILE_B, sB_h = sb + 2 * TILE_B, sB_l = sb + 3 * TILE_B;

        // ldmatrix address offsets
        const uint32_t a_row = (uint32_t)(wm + (lane & 15));
        const uint32_t a_kb  = (uint32_t)(((lane >> 4) << 3) * 2);
        const uint32_t b_row = (uint32_t)(wn + ((lane >> 4) << 3) + (lane & 7));
        const uint32_t b_kb  = (uint32_t)((((lane >> 3) & 1) * 8) * 2);

        #pragma unroll
        for (int ks = 0; ks < 2; ks++) {
            const uint32_t kb = (uint32_t)(ks * 32);
            uint32_t ah[4][4], al[4][4], bh[2][4], bl[2][4];
            #pragma unroll
            for (int mt = 0; mt < 4; mt++) {
                uint32_t ad = (a_row + mt * 16) * RSTRIDE + kb + a_kb;
                LDSM_X4(ah[mt], sA_h + ad);
                LDSM_X4(al[mt], sA_l + ad);
            }
            #pragma unroll
            for (int p = 0; p < 2; p++) {
                uint32_t bd = (b_row + p * 16) * RSTRIDE + kb + b_kb;
                LDSM_X4(bh[p], sB_h + bd);
                LDSM_X4(bl[p], sB_l + bd);
            }
            #pragma unroll
            for (int mt = 0; mt < 4; mt++)
                #pragma unroll
                for (int nt = 0; nt < 4; nt++) {
                    const int p = nt >> 1, o = (nt & 1) * 2;
                    MMA16816(acc[mt][nt], ah[mt], bh[p][o], bh[p][o + 1]);
                    MMA16816(acc[mt][nt], ah[mt], bl[p][o], bl[p][o + 1]);
                    MMA16816(acc[mt][nt], al[mt], bh[p][o], bh[p][o + 1]);
                }
        }
        __syncthreads();
    }

    // epilogue: d0,d1 -> (row, col..col+1), d2,d3 -> (row+8, col..col+1)
    #pragma unroll
    for (int mt = 0; mt < 4; mt++) {
        int row = m0 + wm + mt * 16 + (lane >> 2);
        #pragma unroll
        for (int nt = 0; nt < 4; nt++) {
            int col = n0 + wn + nt * 8 + (lane & 3) * 2;
            #pragma unroll
            for (int half = 0; half < 2; half++) {
                int rr = row + half * 8;
                float v0 = acc[mt][nt][half * 2 + 0];
                float v1 = acc[mt][nt][half * 2 + 1];
                if (col < 2000) {
                    float2 f = make_float2(v0, v1);
                    *reinterpret_cast<float2*>(xcout + (size_t)rr * ED + col) = f;
                } else if (col < 4000) {
                    float2 f = make_float2(fast_silu(v0), fast_silu(v1));
                    *reinterpret_cast<float2*>(szout + (size_t)rr * ED + (col - 2000)) = f;
                }
            }
        }
    }
}

// ---------------- fp32 SGEMM (xproj, delta) ---------------------------------
__global__ void __launch_bounds__(256, 2)
sgemm(const float* __restrict__ A, const float* __restrict__ B,
      int M, int N, int K, int lda, int ldb, int ldc,
      float* __restrict__ C1, const float* __restrict__ bias, int mode)
{
    constexpr int BM = 128, BN = 128, BK = 16, TM = 8, TN = 8;
    __shared__ float As[BK][BM + 4];
    __shared__ float Bs[BK][BN];
    const int t = threadIdx.x;
    const int row0 = blockIdx.y * BM;
    const int col0 = blockIdx.x * BN;
    const int aRow = t >> 2, aCol = (t & 3) * 4;
    const int bRow = t >> 5, bCol = (t & 31) * 4;
    const int ty = t >> 4, tx = t & 15;

    float acc[TM][TN];
    #pragma unroll
    for (int i = 0; i < TM; i++)
        #pragma unroll
        for (int j = 0; j < TN; j++) acc[i][j] = 0.f;

    for (int k0 = 0; k0 < K; k0 += BK) {
        #pragma unroll
        for (int s = 0; s < 2; s++) {
            int r = aRow + s * 64;
            int gk = k0 + aCol;
            float4 v = make_float4(0.f, 0.f, 0.f, 0.f);
            const float* ap = A + (size_t)(row0 + r) * lda + gk;
            if (gk + 0 < K) v.x = ap[0];
            if (gk + 1 < K) v.y = ap[1];
            if (gk + 2 < K) v.z = ap[2];
            if (gk + 3 < K) v.w = ap[3];
            As[aCol + 0][r] = v.x;
            As[aCol + 1][r] = v.y;
            As[aCol + 2][r] = v.z;
            As[aCol + 3][r] = v.w;
        }
        #pragma unroll
        for (int s = 0; s < 2; s++) {
            int r = bRow + s * 8;
            int gk = k0 + r;
            int gc = col0 + bCol;
            float4 v = make_float4(0.f, 0.f, 0.f, 0.f);
            const float* bp = B + (size_t)gk * ldb + gc;
            if (gk < K) {
                if (gc + 0 < N) v.x = bp[0];
                if (gc + 1 < N) v.y = bp[1];
                if (gc + 2 < N) v.z = bp[2];
                if (gc + 3 < N) v.w = bp[3];
            }
            *reinterpret_cast<float4*>(&Bs[r][bCol]) = v;
        }
        __syncthreads();
        #pragma unroll
        for (int kk = 0; kk < BK; kk++) {
            float ra[TM], rb[TN];
            const float4* a4 = reinterpret_cast<const float4*>(&As[kk][ty * TM]);
            float4 a0 = a4[0], a1 = a4[1];
            ra[0]=a0.x; ra[1]=a0.y; ra[2]=a0.z; ra[3]=a0.w;
            ra[4]=a1.x; ra[5]=a1.y; ra[6]=a1.z; ra[7]=a1.w;
            const float4* b4 = reinterpret_cast<const float4*>(&Bs[kk][tx * TN]);
            float4 b0 = b4[0], b1 = b4[1];
            rb[0]=b0.x; rb[1]=b0.y; rb[2]=b0.z; rb[3]=b0.w;
            rb[4]=b1.x; rb[5]=b1.y; rb[6]=b1.z; rb[7]=b1.w;
            #pragma unroll
            for (int i = 0; i < TM; i++)
                #pragma unroll
                for (int j = 0; j < TN; j++)
                    acc[i][j] = fmaf(ra[i], rb[j], acc[i][j]);
        }
        __syncthreads();
    }
    #pragma unroll
    for (int i = 0; i < TM; i++) {
        int gr = row0 + ty * TM + i;
        #pragma unroll
        for (int j = 0; j < TN; j++) {
            int gc = col0 + tx * TN + j;
            if (gc >= N) continue;
            float v = acc[i][j];
            if (mode == 0) C1[(size_t)gr * ldc + gc] = v;
            else           C1[(size_t)gr * ldc + gc] = fast_softplus(v + bias[gc]);
        }
    }
}

// ---------------- depthwise causal conv1d + silu ----------------------------
__global__ void conv_silu_kernel(const float* __restrict__ cw, const float* __restrict__ cb) {
    size_t idx = (size_t)blockIdx.x * blockDim.x + threadIdx.x;
    if (idx >= (size_t)ROWS * ED) return;
    int e = (int)(idx % ED);
    size_t bl = idx / ED;
    int l = (int)(bl % L_);
    float acc = cb[e];
    #pragma unroll
    for (int k = 0; k < 4; k++) {
        int ls = l - 3 + k;
        if (ls >= 0)
            acc = fmaf(g_xcin[idx + (size_t)(ls - l) * ED], cw[e * 4 + k], acc);
    }
    g_xcs[idx] = fast_silu(acc);
}

// ---------------- chunked selective scan: part 1 ----------------------------
__global__ void scan1_kernel(const float* __restrict__ A_log, const float* __restrict__ Dp) {
    int e = blockIdx.x * 256 + threadIdx.x;
    int b = blockIdx.y;
    int c = blockIdx.z;
    if (e >= ED) return;
    float A[NSTATE], h[NSTATE], cum[NSTATE], rr[NSTATE];
    #pragma unroll
    for (int n = 0; n < NSTATE; n++) {
        A[n] = -__expf(A_log[e * NSTATE + n]);
        h[n] = 0.f; cum[n] = 1.f; rr[n] = 0.f;
    }
    float dpe = Dp[e];
    float lacc = 0.f;
    size_t base = ((size_t)(b * L_ + c * TCH)) * ED + e;
    const float* dbcr = g_dbc + (size_t)(b * L_ + c * TCH) * NXP;
    for (int l = 0; l < TCH; l++) {
        float d   = g_delta[base];
        float xv  = g_xcs[base];
        float szv = g_sz[base];
        float dx = d * xv;
        float y = 0.f;
        #pragma unroll
        for (int n = 0; n < NSTATE; n++) {
            float Bn = dbcr[DTR + n];
            float Cn = dbcr[DTR + NSTATE + n];
            float a = fast_exp(d * A[n]);
            cum[n] *= a;
            h[n] = fmaf(a, h[n], dx * Bn);
            y = fmaf(h[n], Cn, y);
            rr[n] = fmaf(cum[n], Cn * szv, rr[n]);
        }
        lacc = fmaf(y + dpe * xv, szv, lacc);
        base += ED;
        dbcr += NXP;
    }
    int bc = b * CH + c;
    g_sacc[bc * ED + e] = lacc;
    #pragma unroll
    for (int n = 0; n < NSTATE; n++) {
        size_t o = ((size_t)bc * NSTATE + n) * ED + e;
        g_sP[o] = cum[n];
        g_sr[o] = rr[n];
        g_sq[o] = h[n];
    }
}

// ---------------- chunked selective scan: part 2 ----------------------------
__global__ void scan2_kernel() {
    int idx = blockIdx.x * 256 + threadIdx.x;
    if (idx >= B_ * ED) return;
    int b = idx / ED, e = idx % ED;
    float h[NSTATE];
    #pragma unroll
    for (int n = 0; n < NSTATE; n++) h[n] = 0.f;
    float acc = 0.f;
    for (int c = 0; c < CH; c++) {
        int bc = b * CH + c;
        acc += g_sacc[bc * ED + e];
        #pragma unroll
        for (int n = 0; n < NSTATE; n++) {
            size_t o = ((size_t)bc * NSTATE + n) * ED + e;
            acc = fmaf(h[n], g_sr[o], acc);
            h[n] = fmaf(g_sP[o], h[n], g_sq[o]);
        }
    }
    g_ybar[idx] = acc * (1.0f / L_);
}

// ---------------- tail kernels ----------------------------------------------
__global__ void xbar_kernel(const float* __restrict__ x) {
    int idx = blockIdx.x * blockDim.x + threadIdx.x;
    if (idx >= B_ * DM) return;
    int b = idx / DM, d = idx % DM;
    const float* p = x + (size_t)b * L_ * DM + d;
    float s = 0.f;
    #pragma unroll 8
    for (int l = 0; l < L_; l++) s += p[(size_t)l * DM];
    g_xbar[idx] = s * (1.f / L_);
}

__global__ void out_e_kernel(const float* __restrict__ W_outp) {
    int idx = blockIdx.x * blockDim.x + threadIdx.x;
    if (idx >= B_ * DM) return;
    int b = idx / DM, d = idx % DM;
    float acc = g_xbar[idx];
    const float* yb = g_ybar + b * ED;
    #pragma unroll 8
    for (int e = 0; e < ED; e++)
        acc = fmaf(yb[e], W_outp[(size_t)e * DM + d], acc);
    g_e[idx] = acc;
}

__global__ void out_h_kernel(const float* __restrict__ W_fc, const float* __restrict__ b_fc,
                             float* __restrict__ out) {
    int idx = blockIdx.x * blockDim.x + threadIdx.x;
    if (idx >= B_ * DM) return;
    int b = idx / DM, d = idx % DM;
    float acc = b_fc[d];
    const float* er = g_e + b * DM;
    #pragma unroll 8
    for (int k = 0; k < DM; k++)
        acc = fmaf(er[k], W_fc[(size_t)k * DM + d], acc);
    float th = tanhf(acc);
    out[idx] = (th > 0.f) ? th : expm1f(th);
}

__global__ void out_musig_kernel(const float* __restrict__ W_mu, const float* __restrict__ b_mu,
                                 const float* __restrict__ W_sig, const float* __restrict__ b_sig,
                                 float* __restrict__ out) {
    int idx = blockIdx.x * blockDim.x + threadIdx.x;
    if (idx >= B_ * 2 * NOUT) return;
    int b = idx / (2 * NOUT);
    int r = idx % (2 * NOUT);
    const float* h = out + b * DM;
    if (r < NOUT) {
        float acc = b_mu[r];
        #pragma unroll 8
        for (int k = 0; k < DM; k++)
            acc = fmaf(h[k], W_mu[(size_t)k * NOUT + r], acc);
        out[B_ * DM + b * NOUT + r] = acc;
    } else {
        int j = r - NOUT;
        float acc = b_sig[j];
        #pragma unroll 8
        for (int k = 0; k < DM; k++)
            acc = fmaf(h[k], W_sig[(size_t)k * NOUT + j], acc);
        float el = (acc > 0.f) ? acc : expm1f(acc);
        out[B_ * DM + B_ * NOUT + b * NOUT + j] = el + 1.0f + 1e-14f;
    }
}

// ---------------- launcher ----------------------------------------------------
extern "C" void kernel_launch(void* const* d_in, const int* in_sizes, int n_in,
                              void* d_out, int out_size) {
    (void)in_sizes; (void)n_in; (void)out_size;
    const float* x      = (const float*)d_in[0];
    const float* w_norm = (const float*)d_in[1];
    const float* W_in   = (const float*)d_in[2];
    const float* conv_w = (const float*)d_in[3];
    const float* conv_b = (const float*)d_in[4];
    const float* W_xproj= (const float*)d_in[5];
    const float* W_dt   = (const float*)d_in[6];
    const float* b_dt   = (const float*)d_in[7];
    const float* A_log  = (const float*)d_in[8];
    const float* Dp     = (const float*)d_in[9];
    const float* W_outp = (const float*)d_in[10];
    const float* W_fc   = (const float*)d_in[11];
    const float* b_fc   = (const float*)d_in[12];
    const float* W_mu   = (const float*)d_in[13];
    const float* b_mu   = (const float*)d_in[14];
    const float* W_sig  = (const float*)d_in[15];
    const float* b_sig  = (const float*)d_in[16];
    float* out = (float*)d_out;

    float *p_xcin, *p_sz, *p_xcs, *p_delta, *p_dbc;
    __nv_bfloat16 *p_Ah, *p_Al, *p_Wh, *p_Wl;
    cudaGetSymbolAddress((void**)&p_xcin,  g_xcin);
    cudaGetSymbolAddress((void**)&p_sz,    g_sz);
    cudaGetSymbolAddress((void**)&p_xcs,   g_xcs);
    cudaGetSymbolAddress((void**)&p_delta, g_delta);
    cudaGetSymbolAddress((void**)&p_dbc,   g_dbc);
    cudaGetSymbolAddress((void**)&p_Ah,    g_Ah);
    cudaGetSymbolAddress((void**)&p_Al,    g_Al);
    cudaGetSymbolAddress((void**)&p_Wh,    g_Wh);
    cudaGetSymbolAddress((void**)&p_Wl,    g_Wl);

    cudaFuncSetAttribute(gemm_mma_kernel, cudaFuncAttributeMaxDynamicSharedMemorySize, GEMM_SMEM);

    // 1) rmsnorm + bf16 hi/lo A
    rms_cvt_kernel<<<ROWS, 256>>>(x, w_norm);
    // 2) W_in transpose + bf16 hi/lo
    wcvt_kernel<<<(GN * GK + 255) / 256, 256>>>(W_in);
    // 3) xz = xn @ W_in via mma.sync (split xc | silu(z))
    {
        dim3 grid(GN / 128, ROWS / 128);
        gemm_mma_kernel<<<grid, 256, GEMM_SMEM>>>(p_Ah, p_Al, p_Wh, p_Wl, p_xcin, p_sz);
    }
    // 4) depthwise causal conv + silu
    {
        size_t total = (size_t)ROWS * ED;
        conv_silu_kernel<<<(unsigned)((total + 255) / 256), 256>>>(conv_w, conv_b);
    }
    // 5) dbc = xcs @ W_xproj
    {
        dim3 grid(1, ROWS / 128);
        sgemm<<<grid, 256>>>(p_xcs, W_xproj, ROWS, NXP, ED, ED, NXP, NXP, p_dbc, nullptr, 0);
    }
    // 6) delta = softplus(dt @ W_dt + b_dt)
    {
        dim3 grid((ED + 127) / 128, ROWS / 128);
        sgemm<<<grid, 256>>>(p_dbc, W_dt, ROWS, ED, DTR, NXP, ED, ED, p_delta, b_dt, 1);
    }
    // 7) chunked scan
    {
        dim3 g1((ED + 255) / 256, B_, CH);
        scan1_kernel<<<g1, 256>>>(A_log, Dp);
        scan2_kernel<<<(B_ * ED + 255) / 256, 256>>>();
    }
    // 8) tails
    xbar_kernel<<<(B_ * DM + 255) / 256, 256>>>(x);
    out_e_kernel<<<(B_ * DM + 255) / 256, 256>>>(W_outp);
    out_h_kernel<<<(B_ * DM + 255) / 256, 256>>>(W_fc, b_fc, out);
    out_musig_kernel<<<(B_ * 2 * NOUT + 255) / 256, 256>>>(W_mu, b_mu, W_sig, b_sig, out);
}

// round 10
// speedup vs baseline: 1.0051x; 1.0020x over previous
#include <cuda_runtime.h>
#include <cuda_bf16.h>
#include <math.h>
#include <stdint.h>

#define B_    8
#define L_    2048
#define DM    1000
#define ED    2000
#define NSTATE 8
#define DTR   63
#define NXP   79
#define NOUT  64
#define ROWS  (B_*L_)
#define GK    1024
#define GN    4096
#define CH    8
#define TCH   (L_/CH)

// GEMM smem: 2 stages x 4 tiles x (128 rows x 80B)
#define RSTRIDE 80
#define TILE_B  (128*RSTRIDE)
#define STAGE_B (4*TILE_B)
#define GEMM_SMEM (2*STAGE_B)

__device__ __align__(128) __nv_bfloat16 g_Ah[(size_t)ROWS*GK];
__device__ __align__(128) __nv_bfloat16 g_Al[(size_t)ROWS*GK];
__device__ __align__(128) __nv_bfloat16 g_Wh[(size_t)GN*GK];
__device__ __align__(128) __nv_bfloat16 g_Wl[(size_t)GN*GK];
__device__ __align__(128) float g_xcin [(size_t)ROWS*ED];
__device__ __align__(128) float g_sz   [(size_t)ROWS*ED];
__device__ __align__(128) float g_xcs  [(size_t)ROWS*ED];
__device__ __align__(128) float g_delta[(size_t)ROWS*ED];
__device__ __align__(128) float g_dbc  [(size_t)ROWS*NXP];
__device__ __align__(128) float g_sacc [B_*CH*ED];
__device__ __align__(128) float g_sP   [B_*CH*NSTATE*ED];
__device__ __align__(128) float g_sr   [B_*CH*NSTATE*ED];
__device__ __align__(128) float g_sq   [B_*CH*NSTATE*ED];
__device__ __align__(128) float g_ybar [B_*ED];
__device__ __align__(128) float g_xbar [B_*DM];
__device__ __align__(128) float g_e    [B_*DM];

// ---------------- fast math (FMA pipe, no MUFU) -----------------------------
__device__ __forceinline__ float fast_exp(float x) {
    float t = x * 1.4426950408889634f;
    t = fminf(fmaxf(t, -125.f), 125.f);
    float r = rintf(t);
    float f = t - r;
    float p =             1.3333558e-3f;
    p = fmaf(p, f, 9.6181291e-3f);
    p = fmaf(p, f, 5.5504109e-2f);
    p = fmaf(p, f, 2.4022651e-1f);
    p = fmaf(p, f, 6.9314718e-1f);
    p = fmaf(p, f, 1.0f);
    return p * __int_as_float(((int)r + 127) << 23);
}
__device__ __forceinline__ float fast_rcp12(float d) { // 1/d, d in (1,2]
    float r = fmaf(d, -0.47058824f, 1.4117647f);
    r = r * fmaf(-d, r, 2.0f);
    r = r * fmaf(-d, r, 2.0f);
    return r;
}
__device__ __forceinline__ float fast_silu(float v) {
    float t = fast_exp(-fabsf(v));
    float r = fast_rcp12(1.0f + t);
    return (v >= 0.f) ? v * r : v * t * r;
}
__device__ __forceinline__ float fast_softplus(float u) {
    if (u > 15.f) return u;
    float v = 1.0f + fast_exp(u);
    int bi = __float_as_int(v);
    int e = ((bi >> 23) & 255) - 127;
    float m = __int_as_float((bi & 0x007FFFFF) | 0x3F800000);
    if (m > 1.4142135f) { m *= 0.5f; e += 1; }
    float x = m - 1.0f;
    float q = -0.1f;
    q = fmaf(q, x,  0.111111111f);
    q = fmaf(q, x, -0.125f);
    q = fmaf(q, x,  0.142857143f);
    q = fmaf(q, x, -0.166666667f);
    q = fmaf(q, x,  0.2f);
    q = fmaf(q, x, -0.25f);
    q = fmaf(q, x,  0.333333333f);
    q = fmaf(q, x, -0.5f);
    q = fmaf(q, x,  1.0f);
    return fmaf((float)e, 0.69314718056f, q * x);
}

// ---------------- PTX helpers (compute_103-safe: no tcgen05) ----------------
__device__ __forceinline__ uint32_t smem_u32(const void* p) {
    uint32_t a;
    asm("{ .reg .u64 t; cvta.to.shared.u64 t, %1; cvt.u32.u64 %0, t; }" : "=r"(a) : "l"(p));
    return a;
}
#define CP_ASYNC16(sa, ga) asm volatile("cp.async.cg.shared.global [%0], [%1], 16;" :: "r"(sa), "l"(ga))
#define CP_COMMIT()        asm volatile("cp.async.commit_group;")
#define CP_WAIT0()         asm volatile("cp.async.wait_group 0;")
#define CP_WAIT1()         asm volatile("cp.async.wait_group 1;")
#define LDSM_X4(r, addr) \
    asm volatile("ldmatrix.sync.aligned.m8n8.x4.shared.b16 {%0,%1,%2,%3}, [%4];" \
        : "=r"((r)[0]), "=r"((r)[1]), "=r"((r)[2]), "=r"((r)[3]) : "r"(addr))
#define MMA16816(d, a, b0, b1) \
    asm volatile("mma.sync.aligned.m16n8k16.row.col.f32.bf16.bf16.f32 " \
        "{%0,%1,%2,%3}, {%4,%5,%6,%7}, {%8,%9}, {%0,%1,%2,%3};" \
        : "+f"((d)[0]), "+f"((d)[1]), "+f"((d)[2]), "+f"((d)[3]) \
        : "r"((a)[0]), "r"((a)[1]), "r"((a)[2]), "r"((a)[3]), "r"(b0), "r"(b1))

// ---------------- rmsnorm + bf16 hi/lo convert ------------------------------
__global__ void rms_cvt_kernel(const float* __restrict__ x, const float* __restrict__ w) {
    int row = blockIdx.x;
    int tid = threadIdx.x;
    const float* xr = x + (size_t)row * DM;
    float s = 0.f;
    for (int d = tid; d < DM; d += 256) { float v = xr[d]; s += v * v; }
    __shared__ float red[256];
    red[tid] = s; __syncthreads();
    for (int st = 128; st > 0; st >>= 1) {
        if (tid < st) red[tid] += red[tid + st];
        __syncthreads();
    }
    float rstd = rsqrtf(red[0] * (1.f / DM) + 1e-5f);
    __nv_bfloat16* oh = g_Ah + (size_t)row * GK;
    __nv_bfloat16* ol = g_Al + (size_t)row * GK;
    for (int d = tid; d < GK; d += 256) {
        float v = (d < DM) ? xr[d] * rstd * w[d] : 0.f;
        __nv_bfloat16 h = __float2bfloat16(v);
        oh[d] = h;
        ol[d] = __float2bfloat16(v - __bfloat162float(h));
    }
}

// ---------------- W_in transpose + hi/lo convert ----------------------------
__global__ void wcvt_kernel(const float* __restrict__ W_in) {
    int idx = blockIdx.x * 256 + threadIdx.x;
    if (idx >= GN * GK) return;
    int n = idx >> 10;
    int k = idx & (GK - 1);
    float v = (n < 2 * ED && k < DM) ? W_in[(size_t)k * (2 * ED) + n] : 0.f;
    __nv_bfloat16 h = __float2bfloat16(v);
    g_Wh[idx] = h;
    g_Wl[idx] = __float2bfloat16(v - __bfloat162float(h));
}

// ---------------- mma.sync bf16 GEMM: xz = xn @ W_in ------------------------
// C[16384 x 4096] = A[16384 x 1024] * W^T (W stored [n][k]).
// 3-term hi/lo split for ~fp32 accuracy. Split epilogue: xc | silu(z).
__global__ void __launch_bounds__(256)
gemm_mma_kernel(const __nv_bfloat16* __restrict__ Ah, const __nv_bfloat16* __restrict__ Al,
                const __nv_bfloat16* __restrict__ Bh, const __nv_bfloat16* __restrict__ Bl,
                float* __restrict__ xcout, float* __restrict__ szout)
{
    extern __shared__ char smem[];
    const uint32_t sbase = smem_u32(smem);
    const int tid = threadIdx.x;
    const int wid = tid >> 5, lane = tid & 31;
    const int m0 = blockIdx.y * 128;
    const int n0 = blockIdx.x * 128;
    const int wm = (wid >> 2) * 64;
    const int wn = (wid & 3) * 32;

    float acc[4][4][4];
    #pragma unroll
    for (int i = 0; i < 4; i++)
        #pragma unroll
        for (int j = 0; j < 4; j++)
            #pragma unroll
            for (int v = 0; v < 4; v++) acc[i][j][v] = 0.f;

    // per-thread load slots: id in [0,512): row=id>>2, chunk=id&3
    const int r0l = tid >> 2, c0l = (tid & 3);
    const int r1l = (tid + 256) >> 2, c1l = ((tid + 256) & 3);

    const int NIT = GK / 32;
    #pragma unroll 1
    for (int it = 0; it < NIT + 1; it++) {
        if (it < NIT) {  // issue async loads for stage `it`
            const int k0 = it * 32;
            const uint32_t sb = sbase + (it & 1) * STAGE_B;
            {
                uint32_t so = (uint32_t)(r0l * RSTRIDE + c0l * 16);
                size_t ga = (size_t)(m0 + r0l) * GK + k0 + c0l * 8;
                size_t gb = (size_t)(n0 + r0l) * GK + k0 + c0l * 8;
                CP_ASYNC16(sb + 0 * TILE_B + so, Ah + ga);
                CP_ASYNC16(sb + 1 * TILE_B + so, Al + ga);
                CP_ASYNC16(sb + 2 * TILE_B + so, Bh + gb);
                CP_ASYNC16(sb + 3 * TILE_B + so, Bl + gb);
            }
            {
                uint32_t so = (uint32_t)(r1l * RSTRIDE + c1l * 16);
                size_t ga = (size_t)(m0 + r1l) * GK + k0 + c1l * 8;
                size_t gb = (size_t)(n0 + r1l) * GK + k0 + c1l * 8;
                CP_ASYNC16(sb + 0 * TILE_B + so, Ah + ga);
                CP_ASYNC16(sb + 1 * TILE_B + so, Al + ga);
                CP_ASYNC16(sb + 2 * TILE_B + so, Bh + gb);
                CP_ASYNC16(sb + 3 * TILE_B + so, Bl + gb);
            }
            CP_COMMIT();
        }
        if (it == 0) continue;
        // compute stage it-1
        if (it < NIT) CP_WAIT1(); else CP_WAIT0();
        __syncthreads();
        const uint32_t sb = sbase + ((it - 1) & 1) * STAGE_B;
        const uint32_t sA_h = sb, sA_l = sb + TILE_B, sB_h = sb + 2 * TILE_B, sB_l = sb + 3 * TILE_B;

        // ldmatrix address offsets
        const uint32_t a_row = (uint32_t)(wm + (lane & 15));
        const uint32_t a_kb  = (uint32_t)(((lane >> 4) << 3) * 2);
        const uint32_t b_row = (uint32_t)(wn + ((lane >> 4) << 3) + (lane & 7));
        const uint32_t b_kb  = (uint32_t)((((lane >> 3) & 1) * 8) * 2);

        #pragma unroll
        for (int ks = 0; ks < 2; ks++) {
            const uint32_t kb = (uint32_t)(ks * 32);
            uint32_t ah[4][4], al[4][4], bh[2][4], bl[2][4];
            #pragma unroll
            for (int mt = 0; mt < 4; mt++) {
                uint32_t ad = (a_row + mt * 16) * RSTRIDE + kb + a_kb;
                LDSM_X4(ah[mt], sA_h + ad);
                LDSM_X4(al[mt], sA_l + ad);
            }
            #pragma unroll
            for (int p = 0; p < 2; p++) {
                uint32_t bd = (b_row + p * 16) * RSTRIDE + kb + b_kb;
                LDSM_X4(bh[p], sB_h + bd);
                LDSM_X4(bl[p], sB_l + bd);
            }
            #pragma unroll
            for (int mt = 0; mt < 4; mt++)
                #pragma unroll
                for (int nt = 0; nt < 4; nt++) {
                    const int p = nt >> 1, o = (nt & 1) * 2;
                    MMA16816(acc[mt][nt], ah[mt], bh[p][o], bh[p][o + 1]);
                    MMA16816(acc[mt][nt], ah[mt], bl[p][o], bl[p][o + 1]);
                    MMA16816(acc[mt][nt], al[mt], bh[p][o], bh[p][o + 1]);
                }
        }
        __syncthreads();
    }

    // epilogue: d0,d1 -> (row, col..col+1), d2,d3 -> (row+8, col..col+1)
    #pragma unroll
    for (int mt = 0; mt < 4; mt++) {
        int row = m0 + wm + mt * 16 + (lane >> 2);
        #pragma unroll
        for (int nt = 0; nt < 4; nt++) {
            int col = n0 + wn + nt * 8 + (lane & 3) * 2;
            #pragma unroll
            for (int half = 0; half < 2; half++) {
                int rr = row + half * 8;
                float v0 = acc[mt][nt][half * 2 + 0];
                float v1 = acc[mt][nt][half * 2 + 1];
                if (col < 2000) {
                    float2 f = make_float2(v0, v1);
                    *reinterpret_cast<float2*>(xcout + (size_t)rr * ED + col) = f;
                } else if (col < 4000) {
                    float2 f = make_float2(fast_silu(v0), fast_silu(v1));
                    *reinterpret_cast<float2*>(szout + (size_t)rr * ED + (col - 2000)) = f;
                }
            }
        }
    }
}

// ---------------- fp32 SGEMM (xproj, delta) ---------------------------------
__global__ void __launch_bounds__(256, 2)
sgemm(const float* __restrict__ A, const float* __restrict__ B,
      int M, int N, int K, int lda, int ldb, int ldc,
      float* __restrict__ C1, const float* __restrict__ bias, int mode)
{
    constexpr int BM = 128, BN = 128, BK = 16, TM = 8, TN = 8;
    __shared__ float As[BK][BM + 4];
    __shared__ float Bs[BK][BN];
    const int t = threadIdx.x;
    const int row0 = blockIdx.y * BM;
    const int col0 = blockIdx.x * BN;
    const int aRow = t >> 2, aCol = (t & 3) * 4;
    const int bRow = t >> 5, bCol = (t & 31) * 4;
    const int ty = t >> 4, tx = t & 15;

    float acc[TM][TN];
    #pragma unroll
    for (int i = 0; i < TM; i++)
        #pragma unroll
        for (int j = 0; j < TN; j++) acc[i][j] = 0.f;

    for (int k0 = 0; k0 < K; k0 += BK) {
        #pragma unroll
        for (int s = 0; s < 2; s++) {
            int r = aRow + s * 64;
            int gk = k0 + aCol;
            float4 v = make_float4(0.f, 0.f, 0.f, 0.f);
            const float* ap = A + (size_t)(row0 + r) * lda + gk;
            if (gk + 0 < K) v.x = ap[0];
            if (gk + 1 < K) v.y = ap[1];
            if (gk + 2 < K) v.z = ap[2];
            if (gk + 3 < K) v.w = ap[3];
            As[aCol + 0][r] = v.x;
            As[aCol + 1][r] = v.y;
            As[aCol + 2][r] = v.z;
            As[aCol + 3][r] = v.w;
        }
        #pragma unroll
        for (int s = 0; s < 2; s++) {
            int r = bRow + s * 8;
            int gk = k0 + r;
            int gc = col0 + bCol;
            float4 v = make_float4(0.f, 0.f, 0.f, 0.f);
            const float* bp = B + (size_t)gk * ldb + gc;
            if (gk < K) {
                if (gc + 0 < N) v.x = bp[0];
                if (gc + 1 < N) v.y = bp[1];
                if (gc + 2 < N) v.z = bp[2];
                if (gc + 3 < N) v.w = bp[3];
            }
            *reinterpret_cast<float4*>(&Bs[r][bCol]) = v;
        }
        __syncthreads();
        #pragma unroll
        for (int kk = 0; kk < BK; kk++) {
            float ra[TM], rb[TN];
            const float4* a4 = reinterpret_cast<const float4*>(&As[kk][ty * TM]);
            float4 a0 = a4[0], a1 = a4[1];
            ra[0]=a0.x; ra[1]=a0.y; ra[2]=a0.z; ra[3]=a0.w;
            ra[4]=a1.x; ra[5]=a1.y; ra[6]=a1.z; ra[7]=a1.w;
            const float4* b4 = reinterpret_cast<const float4*>(&Bs[kk][tx * TN]);
            float4 b0 = b4[0], b1 = b4[1];
            rb[0]=b0.x; rb[1]=b0.y; rb[2]=b0.z; rb[3]=b0.w;
            rb[4]=b1.x; rb[5]=b1.y; rb[6]=b1.z; rb[7]=b1.w;
            #pragma unroll
            for (int i = 0; i < TM; i++)
                #pragma unroll
                for (int j = 0; j < TN; j++)
                    acc[i][j] = fmaf(ra[i], rb[j], acc[i][j]);
        }
        __syncthreads();
    }
    #pragma unroll
    for (int i = 0; i < TM; i++) {
        int gr = row0 + ty * TM + i;
        #pragma unroll
        for (int j = 0; j < TN; j++) {
            int gc = col0 + tx * TN + j;
            if (gc >= N) continue;
            float v = acc[i][j];
            if (mode == 0) C1[(size_t)gr * ldc + gc] = v;
            else           C1[(size_t)gr * ldc + gc] = fast_softplus(v + bias[gc]);
        }
    }
}

// ---------------- depthwise causal conv1d + silu ----------------------------
__global__ void conv_silu_kernel(const float* __restrict__ cw, const float* __restrict__ cb) {
    size_t idx = (size_t)blockIdx.x * blockDim.x + threadIdx.x;
    if (idx >= (size_t)ROWS * ED) return;
    int e = (int)(idx % ED);
    size_t bl = idx / ED;
    int l = (int)(bl % L_);
    float acc = cb[e];
    #pragma unroll
    for (int k = 0; k < 4; k++) {
        int ls = l - 3 + k;
        if (ls >= 0)
            acc = fmaf(g_xcin[idx + (size_t)(ls - l) * ED], cw[e * 4 + k], acc);
    }
    g_xcs[idx] = fast_silu(acc);
}

// ---------------- chunked selective scan: part 1 ----------------------------
__global__ void scan1_kernel(const float* __restrict__ A_log, const float* __restrict__ Dp) {
    int e = blockIdx.x * 256 + threadIdx.x;
    int b = blockIdx.y;
    int c = blockIdx.z;
    if (e >= ED) return;
    float A[NSTATE], h[NSTATE], cum[NSTATE], rr[NSTATE];
    #pragma unroll
    for (int n = 0; n < NSTATE; n++) {
        A[n] = -__expf(A_log[e * NSTATE + n]);
        h[n] = 0.f; cum[n] = 1.f; rr[n] = 0.f;
    }
    float dpe = Dp[e];
    float lacc = 0.f;
    size_t base = ((size_t)(b * L_ + c * TCH)) * ED + e;
    const float* dbcr = g_dbc + (size_t)(b * L_ + c * TCH) * NXP;
    for (int l = 0; l < TCH; l++) {
        float d   = g_delta[base];
        float xv  = g_xcs[base];
        float szv = g_sz[base];
        float dx = d * xv;
        float y = 0.f;
        #pragma unroll
        for (int n = 0; n < NSTATE; n++) {
            float Bn = dbcr[DTR + n];
            float Cn = dbcr[DTR + NSTATE + n];
            float a = fast_exp(d * A[n]);
            cum[n] *= a;
            h[n] = fmaf(a, h[n], dx * Bn);
            y = fmaf(h[n], Cn, y);
            rr[n] = fmaf(cum[n], Cn * szv, rr[n]);
        }
        lacc = fmaf(y + dpe * xv, szv, lacc);
        base += ED;
        dbcr += NXP;
    }
    int bc = b * CH + c;
    g_sacc[bc * ED + e] = lacc;
    #pragma unroll
    for (int n = 0; n < NSTATE; n++) {
        size_t o = ((size_t)bc * NSTATE + n) * ED + e;
        g_sP[o] = cum[n];
        g_sr[o] = rr[n];
        g_sq[o] = h[n];
    }
}

// ---------------- chunked selective scan: part 2 ----------------------------
__global__ void scan2_kernel() {
    int idx = blockIdx.x * 256 + threadIdx.x;
    if (idx >= B_ * ED) return;
    int b = idx / ED, e = idx % ED;
    float h[NSTATE];
    #pragma unroll
    for (int n = 0; n < NSTATE; n++) h[n] = 0.f;
    float acc = 0.f;
    for (int c = 0; c < CH; c++) {
        int bc = b * CH + c;
        acc += g_sacc[bc * ED + e];
        #pragma unroll
        for (int n = 0; n < NSTATE; n++) {
            size_t o = ((size_t)bc * NSTATE + n) * ED + e;
            acc = fmaf(h[n], g_sr[o], acc);
            h[n] = fmaf(g_sP[o], h[n], g_sq[o]);
        }
    }
    g_ybar[idx] = acc * (1.0f / L_);
}

// ---------------- tail kernels ----------------------------------------------
__global__ void xbar_kernel(const float* __restrict__ x) {
    int idx = blockIdx.x * blockDim.x + threadIdx.x;
    if (idx >= B_ * DM) return;
    int b = idx / DM, d = idx % DM;
    const float* p = x + (size_t)b * L_ * DM + d;
    float s = 0.f;
    #pragma unroll 8
    for (int l = 0; l < L_; l++) s += p[(size_t)l * DM];
    g_xbar[idx] = s * (1.f / L_);
}

__global__ void out_e_kernel(const float* __restrict__ W_outp) {
    int idx = blockIdx.x * blockDim.x + threadIdx.x;
    if (idx >= B_ * DM) return;
    int b = idx / DM, d = idx % DM;
    float acc = g_xbar[idx];
    const float* yb = g_ybar + b * ED;
    #pragma unroll 8
    for (int e = 0; e < ED; e++)
        acc = fmaf(yb[e], W_outp[(size_t)e * DM + d], acc);
    g_e[idx] = acc;
}

__global__ void out_h_kernel(const float* __restrict__ W_fc, const float* __restrict__ b_fc,
                             float* __restrict__ out) {
    int idx = blockIdx.x * blockDim.x + threadIdx.x;
    if (idx >= B_ * DM) return;
    int b = idx / DM, d = idx % DM;
    float acc = b_fc[d];
    const float* er = g_e + b * DM;
    #pragma unroll 8
    for (int k = 0; k < DM; k++)
        acc = fmaf(er[k], W_fc[(size_t)k * DM + d], acc);
    float th = tanhf(acc);
    out[idx] = (th > 0.f) ? th : expm1f(th);
}

__global__ void out_musig_kernel(const float* __restrict__ W_mu, const float* __restrict__ b_mu,
                                 const float* __restrict__ W_sig, const float* __restrict__ b_sig,
                                 float* __restrict__ out) {
    int idx = blockIdx.x * blockDim.x + threadIdx.x;
    if (idx >= B_ * 2 * NOUT) return;
    int b = idx / (2 * NOUT);
    int r = idx % (2 * NOUT);
    const float* h = out + b * DM;
    if (r < NOUT) {
        float acc = b_mu[r];
        #pragma unroll 8
        for (int k = 0; k < DM; k++)
            acc = fmaf(h[k], W_mu[(size_t)k * NOUT + r], acc);
        out[B_ * DM + b * NOUT + r] = acc;
    } else {
        int j = r - NOUT;
        float acc = b_sig[j];
        #pragma unroll 8
        for (int k = 0; k < DM; k++)
            acc = fmaf(h[k], W_sig[(size_t)k * NOUT + j], acc);
        float el = (acc > 0.f) ? acc : expm1f(acc);
        out[B_ * DM + B_ * NOUT + b * NOUT + j] = el + 1.0f + 1e-14f;
    }
}

// ---------------- launcher ----------------------------------------------------
extern "C" void kernel_launch(void* const* d_in, const int* in_sizes, int n_in,
                              void* d_out, int out_size) {
    (void)in_sizes; (void)n_in; (void)out_size;
    const float* x      = (const float*)d_in[0];
    const float* w_norm = (const float*)d_in[1];
    const float* W_in   = (const float*)d_in[2];
    const float* conv_w = (const float*)d_in[3];
    const float* conv_b = (const float*)d_in[4];
    const float* W_xproj= (const float*)d_in[5];
    const float* W_dt   = (const float*)d_in[6];
    const float* b_dt   = (const float*)d_in[7];
    const float* A_log  = (const float*)d_in[8];
    const float* Dp     = (const float*)d_in[9];
    const float* W_outp = (const float*)d_in[10];
    const float* W_fc   = (const float*)d_in[11];
    const float* b_fc   = (const float*)d_in[12];
    const float* W_mu   = (const float*)d_in[13];
    const float* b_mu   = (const float*)d_in[14];
    const float* W_sig  = (const float*)d_in[15];
    const float* b_sig  = (const float*)d_in[16];
    float* out = (float*)d_out;

    float *p_xcin, *p_sz, *p_xcs, *p_delta, *p_dbc;
    __nv_bfloat16 *p_Ah, *p_Al, *p_Wh, *p_Wl;
    cudaGetSymbolAddress((void**)&p_xcin,  g_xcin);
    cudaGetSymbolAddress((void**)&p_sz,    g_sz);
    cudaGetSymbolAddress((void**)&p_xcs,   g_xcs);
    cudaGetSymbolAddress((void**)&p_delta, g_delta);
    cudaGetSymbolAddress((void**)&p_dbc,   g_dbc);
    cudaGetSymbolAddress((void**)&p_Ah,    g_Ah);
    cudaGetSymbolAddress((void**)&p_Al,    g_Al);
    cudaGetSymbolAddress((void**)&p_Wh,    g_Wh);
    cudaGetSymbolAddress((void**)&p_Wl,    g_Wl);

    cudaFuncSetAttribute(gemm_mma_kernel, cudaFuncAttributeMaxDynamicSharedMemorySize, GEMM_SMEM);

    // 1) rmsnorm + bf16 hi/lo A
    rms_cvt_kernel<<<ROWS, 256>>>(x, w_norm);
    // 2) W_in transpose + bf16 hi/lo
    wcvt_kernel<<<(GN * GK + 255) / 256, 256>>>(W_in);
    // 3) xz = xn @ W_in via mma.sync (split xc | silu(z))
    {
        dim3 grid(GN / 128, ROWS / 128);
        gemm_mma_kernel<<<grid, 256, GEMM_SMEM>>>(p_Ah, p_Al, p_Wh, p_Wl, p_xcin, p_sz);
    }
    // 4) depthwise causal conv + silu
    {
        size_t total = (size_t)ROWS * ED;
        conv_silu_kernel<<<(unsigned)((total + 255) / 256), 256>>>(conv_w, conv_b);
    }
    // 5) dbc = xcs @ W_xproj
    {
        dim3 grid(1, ROWS / 128);
        sgemm<<<grid, 256>>>(p_xcs, W_xproj, ROWS, NXP, ED, ED, NXP, NXP, p_dbc, nullptr, 0);
    }
    // 6) delta = softplus(dt @ W_dt + b_dt)
    {
        dim3 grid((ED + 127) / 128, ROWS / 128);
        sgemm<<<grid, 256>>>(p_dbc, W_dt, ROWS, ED, DTR, NXP, ED, ED, p_delta, b_dt, 1);
    }
    // 7) chunked scan
    {
        dim3 g1((ED + 255) / 256, B_, CH);
        scan1_kernel<<<g1, 256>>>(A_log, Dp);
        scan2_kernel<<<(B_ * ED + 255) / 256, 256>>>();
    }
    // 8) tails
    xbar_kernel<<<(B_ * DM + 255) / 256, 256>>>(x);
    out_e_kernel<<<(B_ * DM + 255) / 256, 256>>>(W_outp);
    out_h_kernel<<<(B_ * DM + 255) / 256, 256>>>(W_fc, b_fc, out);
    out_musig_kernel<<<(B_ * 2 * NOUT + 255) / 256, 256>>>(W_mu, b_mu, W_sig, b_sig, out);
}

// round 11
// speedup vs baseline: 1.0071x; 1.0020x over previous
#include <cuda_runtime.h>
#include <cuda_bf16.h>
#include <math.h>
#include <stdint.h>

#define B_    8
#define L_    2048
#define DM    1000
#define ED    2000
#define NSTATE 8
#define DTR   63
#define NXP   79
#define NOUT  64
#define ROWS  (B_*L_)
#define GK    1024
#define GN    4096
#define CH    8
#define TCH   (L_/CH)

// GEMM smem: 2 stages x 4 tiles x (128 rows x 80B)
#define RSTRIDE 80
#define TILE_B  (128*RSTRIDE)
#define STAGE_B (4*TILE_B)
#define GEMM_SMEM (2*STAGE_B)

__device__ __align__(128) __nv_bfloat16 g_Ah[(size_t)ROWS*GK];
__device__ __align__(128) __nv_bfloat16 g_Al[(size_t)ROWS*GK];
__device__ __align__(128) __nv_bfloat16 g_Wh[(size_t)GN*GK];
__device__ __align__(128) __nv_bfloat16 g_Wl[(size_t)GN*GK];
__device__ __align__(128) float g_xcin [(size_t)ROWS*ED];
__device__ __align__(128) float g_sz   [(size_t)ROWS*ED];
__device__ __align__(128) float g_xcs  [(size_t)ROWS*ED];
__device__ __align__(128) float g_delta[(size_t)ROWS*ED];
__device__ __align__(128) float g_dbc  [(size_t)ROWS*NXP];
__device__ __align__(128) float g_sacc [B_*CH*ED];
__device__ __align__(128) float g_sP   [B_*CH*NSTATE*ED];
__device__ __align__(128) float g_sr   [B_*CH*NSTATE*ED];
__device__ __align__(128) float g_sq   [B_*CH*NSTATE*ED];
__device__ __align__(128) float g_ybar [B_*ED];
__device__ __align__(128) float g_xbar [B_*DM];
__device__ __align__(128) float g_e    [B_*DM];

// ---------------- fast math (FMA pipe, no MUFU) -----------------------------
__device__ __forceinline__ float fast_exp(float x) {
    float t = x * 1.4426950408889634f;
    t = fminf(fmaxf(t, -125.f), 125.f);
    float r = rintf(t);
    float f = t - r;
    float p =             1.3333558e-3f;
    p = fmaf(p, f, 9.6181291e-3f);
    p = fmaf(p, f, 5.5504109e-2f);
    p = fmaf(p, f, 2.4022651e-1f);
    p = fmaf(p, f, 6.9314718e-1f);
    p = fmaf(p, f, 1.0f);
    return p * __int_as_float(((int)r + 127) << 23);
}
__device__ __forceinline__ float fast_rcp12(float d) { // 1/d, d in (1,2]
    float r = fmaf(d, -0.47058824f, 1.4117647f);
    r = r * fmaf(-d, r, 2.0f);
    r = r * fmaf(-d, r, 2.0f);
    return r;
}
__device__ __forceinline__ float fast_silu(float v) {
    float t = fast_exp(-fabsf(v));
    float r = fast_rcp12(1.0f + t);
    return (v >= 0.f) ? v * r : v * t * r;
}
__device__ __forceinline__ float fast_softplus(float u) {
    if (u > 15.f) return u;
    float v = 1.0f + fast_exp(u);
    int bi = __float_as_int(v);
    int e = ((bi >> 23) & 255) - 127;
    float m = __int_as_float((bi & 0x007FFFFF) | 0x3F800000);
    if (m > 1.4142135f) { m *= 0.5f; e += 1; }
    float x = m - 1.0f;
    float q = -0.1f;
    q = fmaf(q, x,  0.111111111f);
    q = fmaf(q, x, -0.125f);
    q = fmaf(q, x,  0.142857143f);
    q = fmaf(q, x, -0.166666667f);
    q = fmaf(q, x,  0.2f);
    q = fmaf(q, x, -0.25f);
    q = fmaf(q, x,  0.333333333f);
    q = fmaf(q, x, -0.5f);
    q = fmaf(q, x,  1.0f);
    return fmaf((float)e, 0.69314718056f, q * x);
}

// ---------------- PTX helpers (compute_103-safe: no tcgen05) ----------------
__device__ __forceinline__ uint32_t smem_u32(const void* p) {
    uint32_t a;
    asm("{ .reg .u64 t; cvta.to.shared.u64 t, %1; cvt.u32.u64 %0, t; }" : "=r"(a) : "l"(p));
    return a;
}
#define CP_ASYNC16(sa, ga) asm volatile("cp.async.cg.shared.global [%0], [%1], 16;" :: "r"(sa), "l"(ga))
#define CP_COMMIT()        asm volatile("cp.async.commit_group;")
#define CP_WAIT0()         asm volatile("cp.async.wait_group 0;")
#define CP_WAIT1()         asm volatile("cp.async.wait_group 1;")
#define LDSM_X4(r, addr) \
    asm volatile("ldmatrix.sync.aligned.m8n8.x4.shared.b16 {%0,%1,%2,%3}, [%4];" \
        : "=r"((r)[0]), "=r"((r)[1]), "=r"((r)[2]), "=r"((r)[3]) : "r"(addr))
#define MMA16816(d, a, b0, b1) \
    asm volatile("mma.sync.aligned.m16n8k16.row.col.f32.bf16.bf16.f32 " \
        "{%0,%1,%2,%3}, {%4,%5,%6,%7}, {%8,%9}, {%0,%1,%2,%3};" \
        : "+f"((d)[0]), "+f"((d)[1]), "+f"((d)[2]), "+f"((d)[3]) \
        : "r"((a)[0]), "r"((a)[1]), "r"((a)[2]), "r"((a)[3]), "r"(b0), "r"(b1))

// ---------------- rmsnorm + bf16 hi/lo convert ------------------------------
__global__ void rms_cvt_kernel(const float* __restrict__ x, const float* __restrict__ w) {
    int row = blockIdx.x;
    int tid = threadIdx.x;
    const float* xr = x + (size_t)row * DM;
    float s = 0.f;
    for (int d = tid; d < DM; d += 256) { float v = xr[d]; s += v * v; }
    __shared__ float red[256];
    red[tid] = s; __syncthreads();
    for (int st = 128; st > 0; st >>= 1) {
        if (tid < st) red[tid] += red[tid + st];
        __syncthreads();
    }
    float rstd = rsqrtf(red[0] * (1.f / DM) + 1e-5f);
    __nv_bfloat16* oh = g_Ah + (size_t)row * GK;
    __nv_bfloat16* ol = g_Al + (size_t)row * GK;
    for (int d = tid; d < GK; d += 256) {
        float v = (d < DM) ? xr[d] * rstd * w[d] : 0.f;
        __nv_bfloat16 h = __float2bfloat16(v);
        oh[d] = h;
        ol[d] = __float2bfloat16(v - __bfloat162float(h));
    }
}

// ---------------- W_in transpose + hi/lo convert ----------------------------
__global__ void wcvt_kernel(const float* __restrict__ W_in) {
    int idx = blockIdx.x * 256 + threadIdx.x;
    if (idx >= GN * GK) return;
    int n = idx >> 10;
    int k = idx & (GK - 1);
    float v = (n < 2 * ED && k < DM) ? W_in[(size_t)k * (2 * ED) + n] : 0.f;
    __nv_bfloat16 h = __float2bfloat16(v);
    g_Wh[idx] = h;
    g_Wl[idx] = __float2bfloat16(v - __bfloat162float(h));
}

// ---------------- mma.sync bf16 GEMM: xz = xn @ W_in ------------------------
// C[16384 x 4096] = A[16384 x 1024] * W^T (W stored [n][k]).
// 3-term hi/lo split for ~fp32 accuracy. Split epilogue: xc | silu(z).
__global__ void __launch_bounds__(256)
gemm_mma_kernel(const __nv_bfloat16* __restrict__ Ah, const __nv_bfloat16* __restrict__ Al,
                const __nv_bfloat16* __restrict__ Bh, const __nv_bfloat16* __restrict__ Bl,
                float* __restrict__ xcout, float* __restrict__ szout)
{
    extern __shared__ char smem[];
    const uint32_t sbase = smem_u32(smem);
    const int tid = threadIdx.x;
    const int wid = tid >> 5, lane = tid & 31;
    const int m0 = blockIdx.y * 128;
    const int n0 = blockIdx.x * 128;
    const int wm = (wid >> 2) * 64;
    const int wn = (wid & 3) * 32;

    float acc[4][4][4];
    #pragma unroll
    for (int i = 0; i < 4; i++)
        #pragma unroll
        for (int j = 0; j < 4; j++)
            #pragma unroll
            for (int v = 0; v < 4; v++) acc[i][j][v] = 0.f;

    // per-thread load slots: id in [0,512): row=id>>2, chunk=id&3
    const int r0l = tid >> 2, c0l = (tid & 3);
    const int r1l = (tid + 256) >> 2, c1l = ((tid + 256) & 3);

    const int NIT = GK / 32;
    #pragma unroll 1
    for (int it = 0; it < NIT + 1; it++) {
        if (it < NIT) {  // issue async loads for stage `it`
            const int k0 = it * 32;
            const uint32_t sb = sbase + (it & 1) * STAGE_B;
            {
                uint32_t so = (uint32_t)(r0l * RSTRIDE + c0l * 16);
                size_t ga = (size_t)(m0 + r0l) * GK + k0 + c0l * 8;
                size_t gb = (size_t)(n0 + r0l) * GK + k0 + c0l * 8;
                CP_ASYNC16(sb + 0 * TILE_B + so, Ah + ga);
                CP_ASYNC16(sb + 1 * TILE_B + so, Al + ga);
                CP_ASYNC16(sb + 2 * TILE_B + so, Bh + gb);
                CP_ASYNC16(sb + 3 * TILE_B + so, Bl + gb);
            }
            {
                uint32_t so = (uint32_t)(r1l * RSTRIDE + c1l * 16);
                size_t ga = (size_t)(m0 + r1l) * GK + k0 + c1l * 8;
                size_t gb = (size_t)(n0 + r1l) * GK + k0 + c1l * 8;
                CP_ASYNC16(sb + 0 * TILE_B + so, Ah + ga);
                CP_ASYNC16(sb + 1 * TILE_B + so, Al + ga);
                CP_ASYNC16(sb + 2 * TILE_B + so, Bh + gb);
                CP_ASYNC16(sb + 3 * TILE_B + so, Bl + gb);
            }
            CP_COMMIT();
        }
        if (it == 0) continue;
        // compute stage it-1
        if (it < NIT) CP_WAIT1(); else CP_WAIT0();
        __syncthreads();
        const uint32_t sb = sbase + ((it - 1) & 1) * STAGE_B;
        const uint32_t sA_h = sb, sA_l = sb + TILE_B, sB_h = sb + 2 * TILE_B, sB_l = sb + 3 * TILE_B;

        // ldmatrix address offsets
        const uint32_t a_row = (uint32_t)(wm + (lane & 15));
        const uint32_t a_kb  = (uint32_t)(((lane >> 4) << 3) * 2);
        const uint32_t b_row = (uint32_t)(wn + ((lane >> 4) << 3) + (lane & 7));
        const uint32_t b_kb  = (uint32_t)((((lane >> 3) & 1) * 8) * 2);

        #pragma unroll
        for (int ks = 0; ks < 2; ks++) {
            const uint32_t kb = (uint32_t)(ks * 32);
            uint32_t ah[4][4], al[4][4], bh[2][4], bl[2][4];
            #pragma unroll
            for (int mt = 0; mt < 4; mt++) {
                uint32_t ad = (a_row + mt * 16) * RSTRIDE + kb + a_kb;
                LDSM_X4(ah[mt], sA_h + ad);
                LDSM_X4(al[mt], sA_l + ad);
            }
            #pragma unroll
            for (int p = 0; p < 2; p++) {
                uint32_t bd = (b_row + p * 16) * RSTRIDE + kb + b_kb;
                LDSM_X4(bh[p], sB_h + bd);
                LDSM_X4(bl[p], sB_l + bd);
            }
            #pragma unroll
            for (int mt = 0; mt < 4; mt++)
                #pragma unroll
                for (int nt = 0; nt < 4; nt++) {
                    const int p = nt >> 1, o = (nt & 1) * 2;
                    MMA16816(acc[mt][nt], ah[mt], bh[p][o], bh[p][o + 1]);
                    MMA16816(acc[mt][nt], ah[mt], bl[p][o], bl[p][o + 1]);
                    MMA16816(acc[mt][nt], al[mt], bh[p][o], bh[p][o + 1]);
                }
        }
        __syncthreads();
    }

    // epilogue: d0,d1 -> (row, col..col+1), d2,d3 -> (row+8, col..col+1)
    #pragma unroll
    for (int mt = 0; mt < 4; mt++) {
        int row = m0 + wm + mt * 16 + (lane >> 2);
        #pragma unroll
        for (int nt = 0; nt < 4; nt++) {
            int col = n0 + wn + nt * 8 + (lane & 3) * 2;
            #pragma unroll
            for (int half = 0; half < 2; half++) {
                int rr = row + half * 8;
                float v0 = acc[mt][nt][half * 2 + 0];
                float v1 = acc[mt][nt][half * 2 + 1];
                if (col < 2000) {
                    float2 f = make_float2(v0, v1);
                    *reinterpret_cast<float2*>(xcout + (size_t)rr * ED + col) = f;
                } else if (col < 4000) {
                    float2 f = make_float2(fast_silu(v0), fast_silu(v1));
                    *reinterpret_cast<float2*>(szout + (size_t)rr * ED + (col - 2000)) = f;
                }
            }
        }
    }
}

// ---------------- fp32 SGEMM (xproj, delta) ---------------------------------
__global__ void __launch_bounds__(256, 2)
sgemm(const float* __restrict__ A, const float* __restrict__ B,
      int M, int N, int K, int lda, int ldb, int ldc,
      float* __restrict__ C1, const float* __restrict__ bias, int mode)
{
    constexpr int BM = 128, BN = 128, BK = 16, TM = 8, TN = 8;
    __shared__ float As[BK][BM + 4];
    __shared__ float Bs[BK][BN];
    const int t = threadIdx.x;
    const int row0 = blockIdx.y * BM;
    const int col0 = blockIdx.x * BN;
    const int aRow = t >> 2, aCol = (t & 3) * 4;
    const int bRow = t >> 5, bCol = (t & 31) * 4;
    const int ty = t >> 4, tx = t & 15;

    float acc[TM][TN];
    #pragma unroll
    for (int i = 0; i < TM; i++)
        #pragma unroll
        for (int j = 0; j < TN; j++) acc[i][j] = 0.f;

    for (int k0 = 0; k0 < K; k0 += BK) {
        #pragma unroll
        for (int s = 0; s < 2; s++) {
            int r = aRow + s * 64;
            int gk = k0 + aCol;
            float4 v = make_float4(0.f, 0.f, 0.f, 0.f);
            const float* ap = A + (size_t)(row0 + r) * lda + gk;
            if (gk + 0 < K) v.x = ap[0];
            if (gk + 1 < K) v.y = ap[1];
            if (gk + 2 < K) v.z = ap[2];
            if (gk + 3 < K) v.w = ap[3];
            As[aCol + 0][r] = v.x;
            As[aCol + 1][r] = v.y;
            As[aCol + 2][r] = v.z;
            As[aCol + 3][r] = v.w;
        }
        #pragma unroll
        for (int s = 0; s < 2; s++) {
            int r = bRow + s * 8;
            int gk = k0 + r;
            int gc = col0 + bCol;
            float4 v = make_float4(0.f, 0.f, 0.f, 0.f);
            const float* bp = B + (size_t)gk * ldb + gc;
            if (gk < K) {
                if (gc + 0 < N) v.x = bp[0];
                if (gc + 1 < N) v.y = bp[1];
                if (gc + 2 < N) v.z = bp[2];
                if (gc + 3 < N) v.w = bp[3];
            }
            *reinterpret_cast<float4*>(&Bs[r][bCol]) = v;
        }
        __syncthreads();
        #pragma unroll
        for (int kk = 0; kk < BK; kk++) {
            float ra[TM], rb[TN];
            const float4* a4 = reinterpret_cast<const float4*>(&As[kk][ty * TM]);
            float4 a0 = a4[0], a1 = a4[1];
            ra[0]=a0.x; ra[1]=a0.y; ra[2]=a0.z; ra[3]=a0.w;
            ra[4]=a1.x; ra[5]=a1.y; ra[6]=a1.z; ra[7]=a1.w;
            const float4* b4 = reinterpret_cast<const float4*>(&Bs[kk][tx * TN]);
            float4 b0 = b4[0], b1 = b4[1];
            rb[0]=b0.x; rb[1]=b0.y; rb[2]=b0.z; rb[3]=b0.w;
            rb[4]=b1.x; rb[5]=b1.y; rb[6]=b1.z; rb[7]=b1.w;
            #pragma unroll
            for (int i = 0; i < TM; i++)
                #pragma unroll
                for (int j = 0; j < TN; j++)
                    acc[i][j] = fmaf(ra[i], rb[j], acc[i][j]);
        }
        __syncthreads();
    }
    #pragma unroll
    for (int i = 0; i < TM; i++) {
        int gr = row0 + ty * TM + i;
        #pragma unroll
        for (int j = 0; j < TN; j++) {
            int gc = col0 + tx * TN + j;
            if (gc >= N) continue;
            float v = acc[i][j];
            if (mode == 0) C1[(size_t)gr * ldc + gc] = v;
            else           C1[(size_t)gr * ldc + gc] = fast_softplus(v + bias[gc]);
        }
    }
}

// ---------------- depthwise causal conv1d + silu ----------------------------
__global__ void conv_silu_kernel(const float* __restrict__ cw, const float* __restrict__ cb) {
    size_t idx = (size_t)blockIdx.x * blockDim.x + threadIdx.x;
    if (idx >= (size_t)ROWS * ED) return;
    int e = (int)(idx % ED);
    size_t bl = idx / ED;
    int l = (int)(bl % L_);
    float acc = cb[e];
    #pragma unroll
    for (int k = 0; k < 4; k++) {
        int ls = l - 3 + k;
        if (ls >= 0)
            acc = fmaf(g_xcin[idx + (size_t)(ls - l) * ED], cw[e * 4 + k], acc);
    }
    g_xcs[idx] = fast_silu(acc);
}

// ---------------- chunked selective scan: part 1 ----------------------------
__global__ void scan1_kernel(const float* __restrict__ A_log, const float* __restrict__ Dp) {
    int e = blockIdx.x * 256 + threadIdx.x;
    int b = blockIdx.y;
    int c = blockIdx.z;
    if (e >= ED) return;
    float A[NSTATE], h[NSTATE], cum[NSTATE], rr[NSTATE];
    #pragma unroll
    for (int n = 0; n < NSTATE; n++) {
        A[n] = -__expf(A_log[e * NSTATE + n]);
        h[n] = 0.f; cum[n] = 1.f; rr[n] = 0.f;
    }
    float dpe = Dp[e];
    float lacc = 0.f;
    size_t base = ((size_t)(b * L_ + c * TCH)) * ED + e;
    const float* dbcr = g_dbc + (size_t)(b * L_ + c * TCH) * NXP;
    for (int l = 0; l < TCH; l++) {
        float d   = g_delta[base];
        float xv  = g_xcs[base];
        float szv = g_sz[base];
        float dx = d * xv;
        float y = 0.f;
        #pragma unroll
        for (int n = 0; n < NSTATE; n++) {
            float Bn = dbcr[DTR + n];
            float Cn = dbcr[DTR + NSTATE + n];
            float a = fast_exp(d * A[n]);
            cum[n] *= a;
            h[n] = fmaf(a, h[n], dx * Bn);
            y = fmaf(h[n], Cn, y);
            rr[n] = fmaf(cum[n], Cn * szv, rr[n]);
        }
        lacc = fmaf(y + dpe * xv, szv, lacc);
        base += ED;
        dbcr += NXP;
    }
    int bc = b * CH + c;
    g_sacc[bc * ED + e] = lacc;
    #pragma unroll
    for (int n = 0; n < NSTATE; n++) {
        size_t o = ((size_t)bc * NSTATE + n) * ED + e;
        g_sP[o] = cum[n];
        g_sr[o] = rr[n];
        g_sq[o] = h[n];
    }
}

// ---------------- chunked selective scan: part 2 ----------------------------
__global__ void scan2_kernel() {
    int idx = blockIdx.x * 256 + threadIdx.x;
    if (idx >= B_ * ED) return;
    int b = idx / ED, e = idx % ED;
    float h[NSTATE];
    #pragma unroll
    for (int n = 0; n < NSTATE; n++) h[n] = 0.f;
    float acc = 0.f;
    for (int c = 0; c < CH; c++) {
        int bc = b * CH + c;
        acc += g_sacc[bc * ED + e];
        #pragma unroll
        for (int n = 0; n < NSTATE; n++) {
            size_t o = ((size_t)bc * NSTATE + n) * ED + e;
            acc = fmaf(h[n], g_sr[o], acc);
            h[n] = fmaf(g_sP[o], h[n], g_sq[o]);
        }
    }
    g_ybar[idx] = acc * (1.0f / L_);
}

// ---------------- tail kernels ----------------------------------------------
__global__ void xbar_kernel(const float* __restrict__ x) {
    int idx = blockIdx.x * blockDim.x + threadIdx.x;
    if (idx >= B_ * DM) return;
    int b = idx / DM, d = idx % DM;
    const float* p = x + (size_t)b * L_ * DM + d;
    float s = 0.f;
    #pragma unroll 8
    for (int l = 0; l < L_; l++) s += p[(size_t)l * DM];
    g_xbar[idx] = s * (1.f / L_);
}

__global__ void out_e_kernel(const float* __restrict__ W_outp) {
    int idx = blockIdx.x * blockDim.x + threadIdx.x;
    if (idx >= B_ * DM) return;
    int b = idx / DM, d = idx % DM;
    float acc = g_xbar[idx];
    const float* yb = g_ybar + b * ED;
    #pragma unroll 8
    for (int e = 0; e < ED; e++)
        acc = fmaf(yb[e], W_outp[(size_t)e * DM + d], acc);
    g_e[idx] = acc;
}

__global__ void out_h_kernel(const float* __restrict__ W_fc, const float* __restrict__ b_fc,
                             float* __restrict__ out) {
    int idx = blockIdx.x * blockDim.x + threadIdx.x;
    if (idx >= B_ * DM) return;
    int b = idx / DM, d = idx % DM;
    float acc = b_fc[d];
    const float* er = g_e + b * DM;
    #pragma unroll 8
    for (int k = 0; k < DM; k++)
        acc = fmaf(er[k], W_fc[(size_t)k * DM + d], acc);
    float th = tanhf(acc);
    out[idx] = (th > 0.f) ? th : expm1f(th);
}

__global__ void out_musig_kernel(const float* __restrict__ W_mu, const float* __restrict__ b_mu,
                                 const float* __restrict__ W_sig, const float* __restrict__ b_sig,
                                 float* __restrict__ out) {
    int idx = blockIdx.x * blockDim.x + threadIdx.x;
    if (idx >= B_ * 2 * NOUT) return;
    int b = idx / (2 * NOUT);
    int r = idx % (2 * NOUT);
    const float* h = out + b * DM;
    if (r < NOUT) {
        float acc = b_mu[r];
        #pragma unroll 8
        for (int k = 0; k < DM; k++)
            acc = fmaf(h[k], W_mu[(size_t)k * NOUT + r], acc);
        out[B_ * DM + b * NOUT + r] = acc;
    } else {
        int j = r - NOUT;
        float acc = b_sig[j];
        #pragma unroll 8
        for (int k = 0; k < DM; k++)
            acc = fmaf(h[k], W_sig[(size_t)k * NOUT + j], acc);
        float el = (acc > 0.f) ? acc : expm1f(acc);
        out[B_ * DM + B_ * NOUT + b * NOUT + j] = el + 1.0f + 1e-14f;
    }
}

// ---------------- launcher ----------------------------------------------------
extern "C" void kernel_launch(void* const* d_in, const int* in_sizes, int n_in,
                              void* d_out, int out_size) {
    (void)in_sizes; (void)n_in; (void)out_size;
    const float* x      = (const float*)d_in[0];
    const float* w_norm = (const float*)d_in[1];
    const float* W_in   = (const float*)d_in[2];
    const float* conv_w = (const float*)d_in[3];
    const float* conv_b = (const float*)d_in[4];
    const float* W_xproj= (const float*)d_in[5];
    const float* W_dt   = (const float*)d_in[6];
    const float* b_dt   = (const float*)d_in[7];
    const float* A_log  = (const float*)d_in[8];
    const float* Dp     = (const float*)d_in[9];
    const float* W_outp = (const float*)d_in[10];
    const float* W_fc   = (const float*)d_in[11];
    const float* b_fc   = (const float*)d_in[12];
    const float* W_mu   = (const float*)d_in[13];
    const float* b_mu   = (const float*)d_in[14];
    const float* W_sig  = (const float*)d_in[15];
    const float* b_sig  = (const float*)d_in[16];
    float* out = (float*)d_out;

    float *p_xcin, *p_sz, *p_xcs, *p_delta, *p_dbc;
    __nv_bfloat16 *p_Ah, *p_Al, *p_Wh, *p_Wl;
    cudaGetSymbolAddress((void**)&p_xcin,  g_xcin);
    cudaGetSymbolAddress((void**)&p_sz,    g_sz);
    cudaGetSymbolAddress((void**)&p_xcs,   g_xcs);
    cudaGetSymbolAddress((void**)&p_delta, g_delta);
    cudaGetSymbolAddress((void**)&p_dbc,   g_dbc);
    cudaGetSymbolAddress((void**)&p_Ah,    g_Ah);
    cudaGetSymbolAddress((void**)&p_Al,    g_Al);
    cudaGetSymbolAddress((void**)&p_Wh,    g_Wh);
    cudaGetSymbolAddress((void**)&p_Wl,    g_Wl);

    cudaFuncSetAttribute(gemm_mma_kernel, cudaFuncAttributeMaxDynamicSharedMemorySize, GEMM_SMEM);

    // 1) rmsnorm + bf16 hi/lo A
    rms_cvt_kernel<<<ROWS, 256>>>(x, w_norm);
    // 2) W_in transpose + bf16 hi/lo
    wcvt_kernel<<<(GN * GK + 255) / 256, 256>>>(W_in);
    // 3) xz = xn @ W_in via mma.sync (split xc | silu(z))
    {
        dim3 grid(GN / 128, ROWS / 128);
        gemm_mma_kernel<<<grid, 256, GEMM_SMEM>>>(p_Ah, p_Al, p_Wh, p_Wl, p_xcin, p_sz);
    }
    // 4) depthwise causal conv + silu
    {
        size_t total = (size_t)ROWS * ED;
        conv_silu_kernel<<<(unsigned)((total + 255) / 256), 256>>>(conv_w, conv_b);
    }
    // 5) dbc = xcs @ W_xproj
    {
        dim3 grid(1, ROWS / 128);
        sgemm<<<grid, 256>>>(p_xcs, W_xproj, ROWS, NXP, ED, ED, NXP, NXP, p_dbc, nullptr, 0);
    }
    // 6) delta = softplus(dt @ W_dt + b_dt)
    {
        dim3 grid((ED + 127) / 128, ROWS / 128);
        sgemm<<<grid, 256>>>(p_dbc, W_dt, ROWS, ED, DTR, NXP, ED, ED, p_delta, b_dt, 1);
    }
    // 7) chunked scan
    {
        dim3 g1((ED + 255) / 256, B_, CH);
        scan1_kernel<<<g1, 256>>>(A_log, Dp);
        scan2_kernel<<<(B_ * ED + 255) / 256, 256>>>();
    }
    // 8) tails
    xbar_kernel<<<(B_ * DM + 255) / 256, 256>>>(x);
    out_e_kernel<<<(B_ * DM + 255) / 256, 256>>>(W_outp);
    out_h_kernel<<<(B_ * DM + 255) / 256, 256>>>(W_fc, b_fc, out);
    out_musig_kernel<<<(B_ * 2 * NOUT + 255) / 256, 256>>>(W_mu, b_mu, W_sig, b_sig, out);
}

// round 12
// speedup vs baseline: 1.0079x; 1.0008x over previous
#include <cuda_runtime.h>
#include <cuda_bf16.h>
#include <math.h>
#include <stdint.h>

#define B_    8
#define L_    2048
#define DM    1000
#define ED    2000
#define NSTATE 8
#define DTR   63
#define NXP   79
#define NOUT  64
#define ROWS  (B_*L_)
#define GK    1024
#define GN    4096
#define CH    8
#define TCH   (L_/CH)

// GEMM smem: 2 stages x 4 tiles x (128 rows x 80B)
#define RSTRIDE 80
#define TILE_B  (128*RSTRIDE)
#define STAGE_B (4*TILE_B)
#define GEMM_SMEM (2*STAGE_B)

__device__ __align__(128) __nv_bfloat16 g_Ah[(size_t)ROWS*GK];
__device__ __align__(128) __nv_bfloat16 g_Al[(size_t)ROWS*GK];
__device__ __align__(128) __nv_bfloat16 g_Wh[(size_t)GN*GK];
__device__ __align__(128) __nv_bfloat16 g_Wl[(size_t)GN*GK];
__device__ __align__(128) float g_xcin [(size_t)ROWS*ED];
__device__ __align__(128) float g_sz   [(size_t)ROWS*ED];
__device__ __align__(128) float g_xcs  [(size_t)ROWS*ED];
__device__ __align__(128) float g_delta[(size_t)ROWS*ED];
__device__ __align__(128) float g_dbc  [(size_t)ROWS*NXP];
__device__ __align__(128) float g_sacc [B_*CH*ED];
__device__ __align__(128) float g_sP   [B_*CH*NSTATE*ED];
__device__ __align__(128) float g_sr   [B_*CH*NSTATE*ED];
__device__ __align__(128) float g_sq   [B_*CH*NSTATE*ED];
__device__ __align__(128) float g_ybar [B_*ED];
__device__ __align__(128) float g_xbar [B_*DM];
__device__ __align__(128) float g_e    [B_*DM];

// ---------------- fast math (FMA pipe, no MUFU) -----------------------------
__device__ __forceinline__ float fast_exp(float x) {
    float t = x * 1.4426950408889634f;
    t = fminf(fmaxf(t, -125.f), 125.f);
    float r = rintf(t);
    float f = t - r;
    float p =             1.3333558e-3f;
    p = fmaf(p, f, 9.6181291e-3f);
    p = fmaf(p, f, 5.5504109e-2f);
    p = fmaf(p, f, 2.4022651e-1f);
    p = fmaf(p, f, 6.9314718e-1f);
    p = fmaf(p, f, 1.0f);
    return p * __int_as_float(((int)r + 127) << 23);
}
__device__ __forceinline__ float fast_rcp12(float d) { // 1/d, d in (1,2]
    float r = fmaf(d, -0.47058824f, 1.4117647f);
    r = r * fmaf(-d, r, 2.0f);
    r = r * fmaf(-d, r, 2.0f);
    return r;
}
__device__ __forceinline__ float fast_silu(float v) {
    float t = fast_exp(-fabsf(v));
    float r = fast_rcp12(1.0f + t);
    return (v >= 0.f) ? v * r : v * t * r;
}
__device__ __forceinline__ float fast_softplus(float u) {
    if (u > 15.f) return u;
    float v = 1.0f + fast_exp(u);
    int bi = __float_as_int(v);
    int e = ((bi >> 23) & 255) - 127;
    float m = __int_as_float((bi & 0x007FFFFF) | 0x3F800000);
    if (m > 1.4142135f) { m *= 0.5f; e += 1; }
    float x = m - 1.0f;
    float q = -0.1f;
    q = fmaf(q, x,  0.111111111f);
    q = fmaf(q, x, -0.125f);
    q = fmaf(q, x,  0.142857143f);
    q = fmaf(q, x, -0.166666667f);
    q = fmaf(q, x,  0.2f);
    q = fmaf(q, x, -0.25f);
    q = fmaf(q, x,  0.333333333f);
    q = fmaf(q, x, -0.5f);
    q = fmaf(q, x,  1.0f);
    return fmaf((float)e, 0.69314718056f, q * x);
}

// ---------------- PTX helpers (compute_103-safe: no tcgen05) ----------------
__device__ __forceinline__ uint32_t smem_u32(const void* p) {
    uint32_t a;
    asm("{ .reg .u64 t; cvta.to.shared.u64 t, %1; cvt.u32.u64 %0, t; }" : "=r"(a) : "l"(p));
    return a;
}
#define CP_ASYNC16(sa, ga) asm volatile("cp.async.cg.shared.global [%0], [%1], 16;" :: "r"(sa), "l"(ga))
#define CP_COMMIT()        asm volatile("cp.async.commit_group;")
#define CP_WAIT0()         asm volatile("cp.async.wait_group 0;")
#define CP_WAIT1()         asm volatile("cp.async.wait_group 1;")
#define LDSM_X4(r, addr) \
    asm volatile("ldmatrix.sync.aligned.m8n8.x4.shared.b16 {%0,%1,%2,%3}, [%4];" \
        : "=r"((r)[0]), "=r"((r)[1]), "=r"((r)[2]), "=r"((r)[3]) : "r"(addr))
#define MMA16816(d, a, b0, b1) \
    asm volatile("mma.sync.aligned.m16n8k16.row.col.f32.bf16.bf16.f32 " \
        "{%0,%1,%2,%3}, {%4,%5,%6,%7}, {%8,%9}, {%0,%1,%2,%3};" \
        : "+f"((d)[0]), "+f"((d)[1]), "+f"((d)[2]), "+f"((d)[3]) \
        : "r"((a)[0]), "r"((a)[1]), "r"((a)[2]), "r"((a)[3]), "r"(b0), "r"(b1))

// ---------------- rmsnorm + bf16 hi/lo convert ------------------------------
__global__ void rms_cvt_kernel(const float* __restrict__ x, const float* __restrict__ w) {
    int row = blockIdx.x;
    int tid = threadIdx.x;
    const float* xr = x + (size_t)row * DM;
    float s = 0.f;
    for (int d = tid; d < DM; d += 256) { float v = xr[d]; s += v * v; }
    __shared__ float red[256];
    red[tid] = s; __syncthreads();
    for (int st = 128; st > 0; st >>= 1) {
        if (tid < st) red[tid] += red[tid + st];
        __syncthreads();
    }
    float rstd = rsqrtf(red[0] * (1.f / DM) + 1e-5f);
    __nv_bfloat16* oh = g_Ah + (size_t)row * GK;
    __nv_bfloat16* ol = g_Al + (size_t)row * GK;
    for (int d = tid; d < GK; d += 256) {
        float v = (d < DM) ? xr[d] * rstd * w[d] : 0.f;
        __nv_bfloat16 h = __float2bfloat16(v);
        oh[d] = h;
        ol[d] = __float2bfloat16(v - __bfloat162float(h));
    }
}

// ---------------- W_in transpose + hi/lo convert ----------------------------
__global__ void wcvt_kernel(const float* __restrict__ W_in) {
    int idx = blockIdx.x * 256 + threadIdx.x;
    if (idx >= GN * GK) return;
    int n = idx >> 10;
    int k = idx & (GK - 1);
    float v = (n < 2 * ED && k < DM) ? W_in[(size_t)k * (2 * ED) + n] : 0.f;
    __nv_bfloat16 h = __float2bfloat16(v);
    g_Wh[idx] = h;
    g_Wl[idx] = __float2bfloat16(v - __bfloat162float(h));
}

// ---------------- mma.sync bf16 GEMM: xz = xn @ W_in ------------------------
// C[16384 x 4096] = A[16384 x 1024] * W^T (W stored [n][k]).
// 3-term hi/lo split for ~fp32 accuracy. Split epilogue: xc | silu(z).
__global__ void __launch_bounds__(256)
gemm_mma_kernel(const __nv_bfloat16* __restrict__ Ah, const __nv_bfloat16* __restrict__ Al,
                const __nv_bfloat16* __restrict__ Bh, const __nv_bfloat16* __restrict__ Bl,
                float* __restrict__ xcout, float* __restrict__ szout)
{
    extern __shared__ char smem[];
    const uint32_t sbase = smem_u32(smem);
    const int tid = threadIdx.x;
    const int wid = tid >> 5, lane = tid & 31;
    const int m0 = blockIdx.y * 128;
    const int n0 = blockIdx.x * 128;
    const int wm = (wid >> 2) * 64;
    const int wn = (wid & 3) * 32;

    float acc[4][4][4];
    #pragma unroll
    for (int i = 0; i < 4; i++)
        #pragma unroll
        for (int j = 0; j < 4; j++)
            #pragma unroll
            for (int v = 0; v < 4; v++) acc[i][j][v] = 0.f;

    // per-thread load slots: id in [0,512): row=id>>2, chunk=id&3
    const int r0l = tid >> 2, c0l = (tid & 3);
    const int r1l = (tid + 256) >> 2, c1l = ((tid + 256) & 3);

    const int NIT = GK / 32;
    #pragma unroll 1
    for (int it = 0; it < NIT + 1; it++) {
        if (it < NIT) {  // issue async loads for stage `it`
            const int k0 = it * 32;
            const uint32_t sb = sbase + (it & 1) * STAGE_B;
            {
                uint32_t so = (uint32_t)(r0l * RSTRIDE + c0l * 16);
                size_t ga = (size_t)(m0 + r0l) * GK + k0 + c0l * 8;
                size_t gb = (size_t)(n0 + r0l) * GK + k0 + c0l * 8;
                CP_ASYNC16(sb + 0 * TILE_B + so, Ah + ga);
                CP_ASYNC16(sb + 1 * TILE_B + so, Al + ga);
                CP_ASYNC16(sb + 2 * TILE_B + so, Bh + gb);
                CP_ASYNC16(sb + 3 * TILE_B + so, Bl + gb);
            }
            {
                uint32_t so = (uint32_t)(r1l * RSTRIDE + c1l * 16);
                size_t ga = (size_t)(m0 + r1l) * GK + k0 + c1l * 8;
                size_t gb = (size_t)(n0 + r1l) * GK + k0 + c1l * 8;
                CP_ASYNC16(sb + 0 * TILE_B + so, Ah + ga);
                CP_ASYNC16(sb + 1 * TILE_B + so, Al + ga);
                CP_ASYNC16(sb + 2 * TILE_B + so, Bh + gb);
                CP_ASYNC16(sb + 3 * TILE_B + so, Bl + gb);
            }
            CP_COMMIT();
        }
        if (it == 0) continue;
        // compute stage it-1
        if (it < NIT) CP_WAIT1(); else CP_WAIT0();
        __syncthreads();
        const uint32_t sb = sbase + ((it - 1) & 1) * STAGE_B;
        const uint32_t sA_h = sb, sA_l = sb + TILE_B, sB_h = sb + 2 * TILE_B, sB_l = sb + 3 * TILE_B;

        // ldmatrix address offsets
        const uint32_t a_row = (uint32_t)(wm + (lane & 15));
        const uint32_t a_kb  = (uint32_t)(((lane >> 4) << 3) * 2);
        const uint32_t b_row = (uint32_t)(wn + ((lane >> 4) << 3) + (lane & 7));
        const uint32_t b_kb  = (uint32_t)((((lane >> 3) & 1) * 8) * 2);

        #pragma unroll
        for (int ks = 0; ks < 2; ks++) {
            const uint32_t kb = (uint32_t)(ks * 32);
            uint32_t ah[4][4], al[4][4], bh[2][4], bl[2][4];
            #pragma unroll
            for (int mt = 0; mt < 4; mt++) {
                uint32_t ad = (a_row + mt * 16) * RSTRIDE + kb + a_kb;
                LDSM_X4(ah[mt], sA_h + ad);
                LDSM_X4(al[mt], sA_l + ad);
            }
            #pragma unroll
            for (int p = 0; p < 2; p++) {
                uint32_t bd = (b_row + p * 16) * RSTRIDE + kb + b_kb;
                LDSM_X4(bh[p], sB_h + bd);
                LDSM_X4(bl[p], sB_l + bd);
            }
            #pragma unroll
            for (int mt = 0; mt < 4; mt++)
                #pragma unroll
                for (int nt = 0; nt < 4; nt++) {
                    const int p = nt >> 1, o = (nt & 1) * 2;
                    MMA16816(acc[mt][nt], ah[mt], bh[p][o], bh[p][o + 1]);
                    MMA16816(acc[mt][nt], ah[mt], bl[p][o], bl[p][o + 1]);
                    MMA16816(acc[mt][nt], al[mt], bh[p][o], bh[p][o + 1]);
                }
        }
        __syncthreads();
    }

    // epilogue: d0,d1 -> (row, col..col+1), d2,d3 -> (row+8, col..col+1)
    #pragma unroll
    for (int mt = 0; mt < 4; mt++) {
        int row = m0 + wm + mt * 16 + (lane >> 2);
        #pragma unroll
        for (int nt = 0; nt < 4; nt++) {
            int col = n0 + wn + nt * 8 + (lane & 3) * 2;
            #pragma unroll
            for (int half = 0; half < 2; half++) {
                int rr = row + half * 8;
                float v0 = acc[mt][nt][half * 2 + 0];
                float v1 = acc[mt][nt][half * 2 + 1];
                if (col < 2000) {
                    float2 f = make_float2(v0, v1);
                    *reinterpret_cast<float2*>(xcout + (size_t)rr * ED + col) = f;
                } else if (col < 4000) {
                    float2 f = make_float2(fast_silu(v0), fast_silu(v1));
                    *reinterpret_cast<float2*>(szout + (size_t)rr * ED + (col - 2000)) = f;
                }
            }
        }
    }
}

// ---------------- fp32 SGEMM (xproj, delta) ---------------------------------
__global__ void __launch_bounds__(256, 2)
sgemm(const float* __restrict__ A, const float* __restrict__ B,
      int M, int N, int K, int lda, int ldb, int ldc,
      float* __restrict__ C1, const float* __restrict__ bias, int mode)
{
    constexpr int BM = 128, BN = 128, BK = 16, TM = 8, TN = 8;
    __shared__ float As[BK][BM + 4];
    __shared__ float Bs[BK][BN];
    const int t = threadIdx.x;
    const int row0 = blockIdx.y * BM;
    const int col0 = blockIdx.x * BN;
    const int aRow = t >> 2, aCol = (t & 3) * 4;
    const int bRow = t >> 5, bCol = (t & 31) * 4;
    const int ty = t >> 4, tx = t & 15;

    float acc[TM][TN];
    #pragma unroll
    for (int i = 0; i < TM; i++)
        #pragma unroll
        for (int j = 0; j < TN; j++) acc[i][j] = 0.f;

    for (int k0 = 0; k0 < K; k0 += BK) {
        #pragma unroll
        for (int s = 0; s < 2; s++) {
            int r = aRow + s * 64;
            int gk = k0 + aCol;
            float4 v = make_float4(0.f, 0.f, 0.f, 0.f);
            const float* ap = A + (size_t)(row0 + r) * lda + gk;
            if (gk + 0 < K) v.x = ap[0];
            if (gk + 1 < K) v.y = ap[1];
            if (gk + 2 < K) v.z = ap[2];
            if (gk + 3 < K) v.w = ap[3];
            As[aCol + 0][r] = v.x;
            As[aCol + 1][r] = v.y;
            As[aCol + 2][r] = v.z;
            As[aCol + 3][r] = v.w;
        }
        #pragma unroll
        for (int s = 0; s < 2; s++) {
            int r = bRow + s * 8;
            int gk = k0 + r;
            int gc = col0 + bCol;
            float4 v = make_float4(0.f, 0.f, 0.f, 0.f);
            const float* bp = B + (size_t)gk * ldb + gc;
            if (gk < K) {
                if (gc + 0 < N) v.x = bp[0];
                if (gc + 1 < N) v.y = bp[1];
                if (gc + 2 < N) v.z = bp[2];
                if (gc + 3 < N) v.w = bp[3];
            }
            *reinterpret_cast<float4*>(&Bs[r][bCol]) = v;
        }
        __syncthreads();
        #pragma unroll
        for (int kk = 0; kk < BK; kk++) {
            float ra[TM], rb[TN];
            const float4* a4 = reinterpret_cast<const float4*>(&As[kk][ty * TM]);
            float4 a0 = a4[0], a1 = a4[1];
            ra[0]=a0.x; ra[1]=a0.y; ra[2]=a0.z; ra[3]=a0.w;
            ra[4]=a1.x; ra[5]=a1.y; ra[6]=a1.z; ra[7]=a1.w;
            const float4* b4 = reinterpret_cast<const float4*>(&Bs[kk][tx * TN]);
            float4 b0 = b4[0], b1 = b4[1];
            rb[0]=b0.x; rb[1]=b0.y; rb[2]=b0.z; rb[3]=b0.w;
            rb[4]=b1.x; rb[5]=b1.y; rb[6]=b1.z; rb[7]=b1.w;
            #pragma unroll
            for (int i = 0; i < TM; i++)
                #pragma unroll
                for (int j = 0; j < TN; j++)
                    acc[i][j] = fmaf(ra[i], rb[j], acc[i][j]);
        }
        __syncthreads();
    }
    #pragma unroll
    for (int i = 0; i < TM; i++) {
        int gr = row0 + ty * TM + i;
        #pragma unroll
        for (int j = 0; j < TN; j++) {
            int gc = col0 + tx * TN + j;
            if (gc >= N) continue;
            float v = acc[i][j];
            if (mode == 0) C1[(size_t)gr * ldc + gc] = v;
            else           C1[(size_t)gr * ldc + gc] = fast_softplus(v + bias[gc]);
        }
    }
}

// ---------------- depthwise causal conv1d + silu ----------------------------
__global__ void conv_silu_kernel(const float* __restrict__ cw, const float* __restrict__ cb) {
    size_t idx = (size_t)blockIdx.x * blockDim.x + threadIdx.x;
    if (idx >= (size_t)ROWS * ED) return;
    int e = (int)(idx % ED);
    size_t bl = idx / ED;
    int l = (int)(bl % L_);
    float acc = cb[e];
    #pragma unroll
    for (int k = 0; k < 4; k++) {
        int ls = l - 3 + k;
        if (ls >= 0)
            acc = fmaf(g_xcin[idx + (size_t)(ls - l) * ED], cw[e * 4 + k], acc);
    }
    g_xcs[idx] = fast_silu(acc);
}

// ---------------- chunked selective scan: part 1 ----------------------------
__global__ void scan1_kernel(const float* __restrict__ A_log, const float* __restrict__ Dp) {
    int e = blockIdx.x * 256 + threadIdx.x;
    int b = blockIdx.y;
    int c = blockIdx.z;
    if (e >= ED) return;
    float A[NSTATE], h[NSTATE], cum[NSTATE], rr[NSTATE];
    #pragma unroll
    for (int n = 0; n < NSTATE; n++) {
        A[n] = -__expf(A_log[e * NSTATE + n]);
        h[n] = 0.f; cum[n] = 1.f; rr[n] = 0.f;
    }
    float dpe = Dp[e];
    float lacc = 0.f;
    size_t base = ((size_t)(b * L_ + c * TCH)) * ED + e;
    const float* dbcr = g_dbc + (size_t)(b * L_ + c * TCH) * NXP;
    for (int l = 0; l < TCH; l++) {
        float d   = g_delta[base];
        float xv  = g_xcs[base];
        float szv = g_sz[base];
        float dx = d * xv;
        float y = 0.f;
        #pragma unroll
        for (int n = 0; n < NSTATE; n++) {
            float Bn = dbcr[DTR + n];
            float Cn = dbcr[DTR + NSTATE + n];
            float a = fast_exp(d * A[n]);
            cum[n] *= a;
            h[n] = fmaf(a, h[n], dx * Bn);
            y = fmaf(h[n], Cn, y);
            rr[n] = fmaf(cum[n], Cn * szv, rr[n]);
        }
        lacc = fmaf(y + dpe * xv, szv, lacc);
        base += ED;
        dbcr += NXP;
    }
    int bc = b * CH + c;
    g_sacc[bc * ED + e] = lacc;
    #pragma unroll
    for (int n = 0; n < NSTATE; n++) {
        size_t o = ((size_t)bc * NSTATE + n) * ED + e;
        g_sP[o] = cum[n];
        g_sr[o] = rr[n];
        g_sq[o] = h[n];
    }
}

// ---------------- chunked selective scan: part 2 ----------------------------
__global__ void scan2_kernel() {
    int idx = blockIdx.x * 256 + threadIdx.x;
    if (idx >= B_ * ED) return;
    int b = idx / ED, e = idx % ED;
    float h[NSTATE];
    #pragma unroll
    for (int n = 0; n < NSTATE; n++) h[n] = 0.f;
    float acc = 0.f;
    for (int c = 0; c < CH; c++) {
        int bc = b * CH + c;
        acc += g_sacc[bc * ED + e];
        #pragma unroll
        for (int n = 0; n < NSTATE; n++) {
            size_t o = ((size_t)bc * NSTATE + n) * ED + e;
            acc = fmaf(h[n], g_sr[o], acc);
            h[n] = fmaf(g_sP[o], h[n], g_sq[o]);
        }
    }
    g_ybar[idx] = acc * (1.0f / L_);
}

// ---------------- tail kernels ----------------------------------------------
__global__ void xbar_kernel(const float* __restrict__ x) {
    int idx = blockIdx.x * blockDim.x + threadIdx.x;
    if (idx >= B_ * DM) return;
    int b = idx / DM, d = idx % DM;
    const float* p = x + (size_t)b * L_ * DM + d;
    float s = 0.f;
    #pragma unroll 8
    for (int l = 0; l < L_; l++) s += p[(size_t)l * DM];
    g_xbar[idx] = s * (1.f / L_);
}

__global__ void out_e_kernel(const float* __restrict__ W_outp) {
    int idx = blockIdx.x * blockDim.x + threadIdx.x;
    if (idx >= B_ * DM) return;
    int b = idx / DM, d = idx % DM;
    float acc = g_xbar[idx];
    const float* yb = g_ybar + b * ED;
    #pragma unroll 8
    for (int e = 0; e < ED; e++)
        acc = fmaf(yb[e], W_outp[(size_t)e * DM + d], acc);
    g_e[idx] = acc;
}

__global__ void out_h_kernel(const float* __restrict__ W_fc, const float* __restrict__ b_fc,
                             float* __restrict__ out) {
    int idx = blockIdx.x * blockDim.x + threadIdx.x;
    if (idx >= B_ * DM) return;
    int b = idx / DM, d = idx % DM;
    float acc = b_fc[d];
    const float* er = g_e + b * DM;
    #pragma unroll 8
    for (int k = 0; k < DM; k++)
        acc = fmaf(er[k], W_fc[(size_t)k * DM + d], acc);
    float th = tanhf(acc);
    out[idx] = (th > 0.f) ? th : expm1f(th);
}

__global__ void out_musig_kernel(const float* __restrict__ W_mu, const float* __restrict__ b_mu,
                                 const float* __restrict__ W_sig, const float* __restrict__ b_sig,
                                 float* __restrict__ out) {
    int idx = blockIdx.x * blockDim.x + threadIdx.x;
    if (idx >= B_ * 2 * NOUT) return;
    int b = idx / (2 * NOUT);
    int r = idx % (2 * NOUT);
    const float* h = out + b * DM;
    if (r < NOUT) {
        float acc = b_mu[r];
        #pragma unroll 8
        for (int k = 0; k < DM; k++)
            acc = fmaf(h[k], W_mu[(size_t)k * NOUT + r], acc);
        out[B_ * DM + b * NOUT + r] = acc;
    } else {
        int j = r - NOUT;
        float acc = b_sig[j];
        #pragma unroll 8
        for (int k = 0; k < DM; k++)
            acc = fmaf(h[k], W_sig[(size_t)k * NOUT + j], acc);
        float el = (acc > 0.f) ? acc : expm1f(acc);
        out[B_ * DM + B_ * NOUT + b * NOUT + j] = el + 1.0f + 1e-14f;
    }
}

// ---------------- launcher ----------------------------------------------------
extern "C" void kernel_launch(void* const* d_in, const int* in_sizes, int n_in,
                              void* d_out, int out_size) {
    (void)in_sizes; (void)n_in; (void)out_size;
    const float* x      = (const float*)d_in[0];
    const float* w_norm = (const float*)d_in[1];
    const float* W_in   = (const float*)d_in[2];
    const float* conv_w = (const float*)d_in[3];
    const float* conv_b = (const float*)d_in[4];
    const float* W_xproj= (const float*)d_in[5];
    const float* W_dt   = (const float*)d_in[6];
    const float* b_dt   = (const float*)d_in[7];
    const float* A_log  = (const float*)d_in[8];
    const float* Dp     = (const float*)d_in[9];
    const float* W_outp = (const float*)d_in[10];
    const float* W_fc   = (const float*)d_in[11];
    const float* b_fc   = (const float*)d_in[12];
    const float* W_mu   = (const float*)d_in[13];
    const float* b_mu   = (const float*)d_in[14];
    const float* W_sig  = (const float*)d_in[15];
    const float* b_sig  = (const float*)d_in[16];
    float* out = (float*)d_out;

    float *p_xcin, *p_sz, *p_xcs, *p_delta, *p_dbc;
    __nv_bfloat16 *p_Ah, *p_Al, *p_Wh, *p_Wl;
    cudaGetSymbolAddress((void**)&p_xcin,  g_xcin);
    cudaGetSymbolAddress((void**)&p_sz,    g_sz);
    cudaGetSymbolAddress((void**)&p_xcs,   g_xcs);
    cudaGetSymbolAddress((void**)&p_delta, g_delta);
    cudaGetSymbolAddress((void**)&p_dbc,   g_dbc);
    cudaGetSymbolAddress((void**)&p_Ah,    g_Ah);
    cudaGetSymbolAddress((void**)&p_Al,    g_Al);
    cudaGetSymbolAddress((void**)&p_Wh,    g_Wh);
    cudaGetSymbolAddress((void**)&p_Wl,    g_Wl);

    cudaFuncSetAttribute(gemm_mma_kernel, cudaFuncAttributeMaxDynamicSharedMemorySize, GEMM_SMEM);

    // 1) rmsnorm + bf16 hi/lo A
    rms_cvt_kernel<<<ROWS, 256>>>(x, w_norm);
    // 2) W_in transpose + bf16 hi/lo
    wcvt_kernel<<<(GN * GK + 255) / 256, 256>>>(W_in);
    // 3) xz = xn @ W_in via mma.sync (split xc | silu(z))
    {
        dim3 grid(GN / 128, ROWS / 128);
        gemm_mma_kernel<<<grid, 256, GEMM_SMEM>>>(p_Ah, p_Al, p_Wh, p_Wl, p_xcin, p_sz);
    }
    // 4) depthwise causal conv + silu
    {
        size_t total = (size_t)ROWS * ED;
        conv_silu_kernel<<<(unsigned)((total + 255) / 256), 256>>>(conv_w, conv_b);
    }
    // 5) dbc = xcs @ W_xproj
    {
        dim3 grid(1, ROWS / 128);
        sgemm<<<grid, 256>>>(p_xcs, W_xproj, ROWS, NXP, ED, ED, NXP, NXP, p_dbc, nullptr, 0);
    }
    // 6) delta = softplus(dt @ W_dt + b_dt)
    {
        dim3 grid((ED + 127) / 128, ROWS / 128);
        sgemm<<<grid, 256>>>(p_dbc, W_dt, ROWS, ED, DTR, NXP, ED, ED, p_delta, b_dt, 1);
    }
    // 7) chunked scan
    {
        dim3 g1((ED + 255) / 256, B_, CH);
        scan1_kernel<<<g1, 256>>>(A_log, Dp);
        scan2_kernel<<<(B_ * ED + 255) / 256, 256>>>();
    }
    // 8) tails
    xbar_kernel<<<(B_ * DM + 255) / 256, 256>>>(x);
    out_e_kernel<<<(B_ * DM + 255) / 256, 256>>>(W_outp);
    out_h_kernel<<<(B_ * DM + 255) / 256, 256>>>(W_fc, b_fc, out);
    out_musig_kernel<<<(B_ * 2 * NOUT + 255) / 256, 256>>>(W_mu, b_mu, W_sig, b_sig, out);
}